// round 3
// baseline (speedup 1.0000x reference)
#include <cuda_runtime.h>
#include <mma.h>
#include <math.h>

using namespace nvcuda;

// Problem constants
#define Bdim 2
#define Nseq 4096
#define Cdim 1024
#define Hn   16
#define Dd   64
#define W2   10
#define WW   21

#define MROWS (Bdim * Nseq)          // 8192
#define OUT_ELEMS (MROWS * Cdim)     // 8,388,608

// Scratch: device globals (no allocations allowed in kernel_launch)
__device__ float g_Q[OUT_ELEMS];
__device__ float g_K[OUT_ELEMS];
__device__ float g_V[OUT_ELEMS];
__device__ float g_O[OUT_ELEMS];

// ---------------------------------------------------------------------------
// TF32 tensor-core GEMM block:
//   C[m, n] = sum_k A[m, k] * W[n, k] + bias[n]
// A: (8192, 1024) row-major, W: (1024, 1024) row-major (W^T multiply => B is
// effectively col-major KxN, which matches wmma col_major directly).
// Block tile 128x128, K-tile 32, 256 threads = 8 warps (4x2), warp tile 32x64.
// ---------------------------------------------------------------------------
__device__ __forceinline__ void gemm_block_tf32(
    const float* __restrict__ A, const float* __restrict__ W,
    const float* __restrict__ bias, float* __restrict__ C)
{
    constexpr int K     = Cdim;
    constexpr int Nf    = Cdim;
    constexpr int PITCH = 40;   // 32 + 8 pad; rows 160B (32B-aligned fragment ptrs)

    __shared__ __align__(128) float As[128 * PITCH];
    __shared__ __align__(128) float Bs[128 * PITCH];

    const int tid    = threadIdx.x;        // 256 threads
    const int warpId = tid >> 5;
    const int wr     = warpId >> 1;        // 0..3 -> warp row (32 rows each)
    const int wc     = warpId & 1;         // 0..1 -> warp col (64 cols each)
    const int rowBase = blockIdx.y * 128;
    const int colBase = blockIdx.x * 128;

    wmma::fragment<wmma::accumulator, 16, 16, 8, float> acc[2][4];

    // ---- bias init: stage a 16x128 broadcast-bias tile in As (pitch 136,
    //      136*4B = 544B rows; fragment row offsets stay 16B aligned) ----
    for (int idx = tid; idx < 16 * 128; idx += 256) {
        int r = idx >> 7, c = idx & 127;
        As[r * 136 + c] = bias[colBase + c];
    }
    __syncthreads();
#pragma unroll
    for (int i = 0; i < 2; i++)
#pragma unroll
        for (int j = 0; j < 4; j++)
            wmma::load_matrix_sync(acc[i][j], &As[wc * 64 + j * 16], 136,
                                   wmma::mem_row_major);
    __syncthreads();

    // global->smem load mapping: 128x32 tile as 1024 float4, 4 per thread
    const int lr = tid >> 3;               // 0..31
    const int lc = (tid & 7) << 2;         // 0,4,...,28

    for (int kt = 0; kt < K; kt += 32) {
#pragma unroll
        for (int i = 0; i < 4; i++) {
            int r = lr + i * 32;
            *(float4*)&As[r * PITCH + lc] =
                *(const float4*)(A + (size_t)(rowBase + r) * K + kt + lc);
            *(float4*)&Bs[r * PITCH + lc] =
                *(const float4*)(W + (size_t)(colBase + r) * K + kt + lc);
        }
        __syncthreads();

#pragma unroll
        for (int kk = 0; kk < 32; kk += 8) {
            wmma::fragment<wmma::matrix_a, 16, 16, 8, wmma::precision::tf32,
                           wmma::row_major> af[2];
            wmma::fragment<wmma::matrix_b, 16, 16, 8, wmma::precision::tf32,
                           wmma::col_major> bf[4];
#pragma unroll
            for (int i = 0; i < 2; i++) {
                wmma::load_matrix_sync(af[i],
                    &As[(wr * 32 + i * 16) * PITCH + kk], PITCH);
#pragma unroll
                for (int t = 0; t < af[i].num_elements; t++)
                    af[i].x[t] = wmma::__float_to_tf32(af[i].x[t]);
            }
#pragma unroll
            for (int j = 0; j < 4; j++) {
                wmma::load_matrix_sync(bf[j],
                    &Bs[(wc * 64 + j * 16) * PITCH + kk], PITCH);
#pragma unroll
                for (int t = 0; t < bf[j].num_elements; t++)
                    bf[j].x[t] = wmma::__float_to_tf32(bf[j].x[t]);
            }
#pragma unroll
            for (int i = 0; i < 2; i++)
#pragma unroll
                for (int j = 0; j < 4; j++)
                    wmma::mma_sync(acc[i][j], af[i], bf[j], acc[i][j]);
        }
        __syncthreads();
    }

    // ---- store ----
#pragma unroll
    for (int i = 0; i < 2; i++)
#pragma unroll
        for (int j = 0; j < 4; j++) {
            int r = rowBase + wr * 32 + i * 16;
            int c = colBase + wc * 64 + j * 16;
            wmma::store_matrix_sync(&C[(size_t)r * Nf + c], acc[i][j], Nf,
                                    wmma::mem_row_major);
        }
}

// QKV: one launch, blockIdx.z selects {Q, K, V}
__global__ __launch_bounds__(256) void qkv_gemm_kernel(
    const float* __restrict__ X,
    const float* __restrict__ Wq, const float* __restrict__ bq,
    const float* __restrict__ Wk, const float* __restrict__ bk,
    const float* __restrict__ Wv, const float* __restrict__ bv)
{
    const float* W;
    const float* b;
    float* out;
    if (blockIdx.z == 0)      { W = Wq; b = bq; out = g_Q; }
    else if (blockIdx.z == 1) { W = Wk; b = bk; out = g_K; }
    else                      { W = Wv; b = bv; out = g_V; }
    gemm_block_tf32(X, W, b, out);
}

__global__ __launch_bounds__(256) void out_gemm_kernel(
    const float* __restrict__ Wo, const float* __restrict__ bo,
    float* __restrict__ out)
{
    gemm_block_tf32(g_O, Wo, bo, out);
}

// ---------------------------------------------------------------------------
// Local window attention: one warp per (b, h, n) query.
// Lane l owns D-elements {2l, 2l+1} (float2). 21 window scores via warp
// reductions, softmax in registers (replicated per lane), weighted V sum.
// n varies fastest across warps -> adjacent warps reuse K/V rows through L1.
// Emits attn_last = probs[:, :, -1, :11] for n == N-1.
// ---------------------------------------------------------------------------
__global__ __launch_bounds__(256) void attn_kernel(float* __restrict__ attn_last)
{
    const int gwarp = (blockIdx.x * blockDim.x + threadIdx.x) >> 5;
    const int lane  = threadIdx.x & 31;
    const int n  = gwarp & (Nseq - 1);
    const int bh = gwarp >> 12;            // Nseq = 2^12
    const int h  = bh & (Hn - 1);
    const int b  = bh >> 4;

    const size_t base = ((size_t)(b * Nseq + n)) * Cdim + h * Dd;
    const float2 qv = *(const float2*)(g_Q + base + lane * 2);

    float s[WW];
#pragma unroll
    for (int w = 0; w < WW; w++) {
        const int pos = n - W2 + w;
        const bool valid = (unsigned)pos < (unsigned)Nseq;
        float partial = 0.f;
        if (valid) {
            const size_t kb = ((size_t)(b * Nseq + pos)) * Cdim + h * Dd;
            const float2 kv = *(const float2*)(g_K + kb + lane * 2);
            partial = qv.x * kv.x + qv.y * kv.y;
        }
        partial += __shfl_xor_sync(0xffffffffu, partial, 16);
        partial += __shfl_xor_sync(0xffffffffu, partial, 8);
        partial += __shfl_xor_sync(0xffffffffu, partial, 4);
        partial += __shfl_xor_sync(0xffffffffu, partial, 2);
        partial += __shfl_xor_sync(0xffffffffu, partial, 1);
        s[w] = valid ? partial * 0.125f : -INFINITY;   // /sqrt(64)
    }

    float m = s[0];
#pragma unroll
    for (int w = 1; w < WW; w++) m = fmaxf(m, s[w]);
    float sum = 0.f;
#pragma unroll
    for (int w = 0; w < WW; w++) {
        const float e = expf(s[w] - m);   // expf(-inf) == 0 for invalid slots
        s[w] = e;
        sum += e;
    }
    const float inv = 1.f / sum;

    float2 acc = make_float2(0.f, 0.f);
#pragma unroll
    for (int w = 0; w < WW; w++) {
        const int pos = n - W2 + w;
        if ((unsigned)pos < (unsigned)Nseq) {
            const size_t vb = ((size_t)(b * Nseq + pos)) * Cdim + h * Dd;
            const float2 vv = *(const float2*)(g_V + vb + lane * 2);
            const float p = s[w] * inv;
            acc.x += p * vv.x;
            acc.y += p * vv.y;
            if (w <= W2 && n == Nseq - 1 && lane == 0)
                attn_last[(b * Hn + h) * (W2 + 1) + w] = p;
        }
    }
    *(float2*)(g_O + base + lane * 2) = acc;
}

// ---------------------------------------------------------------------------
// Launch: QKV (z=3 fused launch) -> attention -> output projection.
// d_out layout: [out: 8192*1024 floats][attn_last: 2*16*11 floats]
// ---------------------------------------------------------------------------
extern "C" void kernel_launch(void* const* d_in, const int* in_sizes, int n_in,
                              void* d_out, int out_size)
{
    const float* q  = (const float*)d_in[0];
    const float* Wq = (const float*)d_in[1];
    const float* bq = (const float*)d_in[2];
    const float* Wk = (const float*)d_in[3];
    const float* bk = (const float*)d_in[4];
    const float* Wv = (const float*)d_in[5];
    const float* bv = (const float*)d_in[6];
    const float* Wo = (const float*)d_in[7];
    const float* bo = (const float*)d_in[8];
    float* out = (float*)d_out;

    dim3 blk(256);
    dim3 g_qkv(Cdim / 128, MROWS / 128, 3);   // (8, 64, 3)
    qkv_gemm_kernel<<<g_qkv, blk>>>(q, Wq, bq, Wk, bk, Wv, bv);

    const int total_warps = Bdim * Hn * Nseq;          // 131072
    attn_kernel<<<total_warps / 8, 256>>>(out + OUT_ELEMS);

    dim3 g_o(Cdim / 128, MROWS / 128, 1);
    out_gemm_kernel<<<g_o, blk>>>(Wo, bo, out);
}

// round 5
// speedup vs baseline: 1.1682x; 1.1682x over previous
#include <cuda_runtime.h>
#include <cstdint>
#include <mma.h>
#include <math.h>

using namespace nvcuda;

// Problem constants
#define Bdim 2
#define Nseq 4096
#define Cdim 1024
#define Hn   16
#define Dd   64
#define W2   10
#define WW   21

#define MROWS (Bdim * Nseq)          // 8192
#define OUT_ELEMS (MROWS * Cdim)     // 8,388,608

// Scratch: device globals (no allocations allowed in kernel_launch)
__device__ float g_Q[OUT_ELEMS];
__device__ float g_K[OUT_ELEMS];
__device__ float g_V[OUT_ELEMS];
__device__ float g_O[OUT_ELEMS];

// ---------------------------------------------------------------------------
// TF32 tensor-core GEMM with 2-stage cp.async pipeline:
//   C[m, n] = sum_k A[m, k] * W[n, k] + bias[n]
// Block tile 128x128, K-tile 32, 256 threads = 8 warps (4x2), warp tile 32x64.
// Stage layout in dynamic smem: [stage0: As|Bs][stage1: As|Bs], PITCH=40.
// ---------------------------------------------------------------------------
#define PITCH   40                       // 32 + 8 pad floats; rows 160B
#define TILE_F  (128 * PITCH)            // floats per As (or Bs) stage
#define STAGE_F (2 * TILE_F)             // As + Bs
#define SMEM_BYTES (2 * STAGE_F * 4)     // 2 stages = 81920 B

__device__ __forceinline__ void cp16(void* smem_dst, const void* gmem_src)
{
    unsigned d = (unsigned)__cvta_generic_to_shared(smem_dst);
    asm volatile("cp.async.cg.shared.global [%0], [%1], 16;\n"
                 :: "r"(d), "l"(gmem_src));
}

__device__ __forceinline__ void gemm_block_tf32(
    const float* __restrict__ A, const float* __restrict__ W,
    const float* __restrict__ bias, float* __restrict__ C)
{
    constexpr int K  = Cdim;
    constexpr int Nf = Cdim;
    constexpr int NT = K / 32;           // 32 K-tiles

    extern __shared__ float smem[];

    const int tid    = threadIdx.x;      // 256 threads
    const int warpId = tid >> 5;
    const int wr     = warpId >> 1;      // 0..3 -> warp row (32 rows each)
    const int wc     = warpId & 1;       // 0..1 -> warp col (64 cols each)
    const int rowBase = blockIdx.y * 128;
    const int colBase = blockIdx.x * 128;

    wmma::fragment<wmma::accumulator, 16, 16, 8, float> acc[2][4];

    // ---- bias init: 16x128 broadcast tile staged in smem (pitch 128) ----
    for (int idx = tid; idx < 16 * 128; idx += 256) {
        int r = idx >> 7, c = idx & 127;
        smem[r * 128 + c] = bias[colBase + c];
    }
    __syncthreads();
#pragma unroll
    for (int i = 0; i < 2; i++)
#pragma unroll
        for (int j = 0; j < 4; j++)
            wmma::load_matrix_sync(acc[i][j], &smem[wc * 64 + j * 16], 128,
                                   wmma::mem_row_major);
    __syncthreads();

    // global->smem async copy mapping: 128x32 tile = 1024 float4, 4/thread
    const int lr = tid >> 3;             // 0..31
    const int lc = (tid & 7) << 2;       // 0,4,...,28

    // prefetch tile 0 into stage 0
    {
        float* As = smem;
        float* Bs = smem + TILE_F;
#pragma unroll
        for (int i = 0; i < 4; i++) {
            int r = lr + i * 32;
            cp16(&As[r * PITCH + lc], A + (size_t)(rowBase + r) * K + lc);
            cp16(&Bs[r * PITCH + lc], W + (size_t)(colBase + r) * K + lc);
        }
        asm volatile("cp.async.commit_group;\n" ::: "memory");
    }

    for (int kt = 0; kt < NT; kt++) {
        // prefetch next tile into the other stage
        if (kt + 1 < NT) {
            float* As = smem + ((kt + 1) & 1) * STAGE_F;
            float* Bs = As + TILE_F;
            const int k0 = (kt + 1) * 32;
#pragma unroll
            for (int i = 0; i < 4; i++) {
                int r = lr + i * 32;
                cp16(&As[r * PITCH + lc],
                     A + (size_t)(rowBase + r) * K + k0 + lc);
                cp16(&Bs[r * PITCH + lc],
                     W + (size_t)(colBase + r) * K + k0 + lc);
            }
            asm volatile("cp.async.commit_group;\n" ::: "memory");
            asm volatile("cp.async.wait_group 1;\n" ::: "memory");
        } else {
            asm volatile("cp.async.wait_group 0;\n" ::: "memory");
        }
        __syncthreads();   // current stage data visible to all warps

        const float* As = smem + (kt & 1) * STAGE_F;
        const float* Bs = As + TILE_F;

#pragma unroll
        for (int kk = 0; kk < 32; kk += 8) {
            wmma::fragment<wmma::matrix_a, 16, 16, 8, wmma::precision::tf32,
                           wmma::row_major> af[2];
            wmma::fragment<wmma::matrix_b, 16, 16, 8, wmma::precision::tf32,
                           wmma::col_major> bf[4];
#pragma unroll
            for (int i = 0; i < 2; i++) {
                wmma::load_matrix_sync(af[i],
                    &As[(wr * 32 + i * 16) * PITCH + kk], PITCH);
#pragma unroll
                for (int t = 0; t < af[i].num_elements; t++)
                    af[i].x[t] = wmma::__float_to_tf32(af[i].x[t]);
            }
#pragma unroll
            for (int j = 0; j < 4; j++) {
                wmma::load_matrix_sync(bf[j],
                    &Bs[(wc * 64 + j * 16) * PITCH + kk], PITCH);
#pragma unroll
                for (int t = 0; t < bf[j].num_elements; t++)
                    bf[j].x[t] = wmma::__float_to_tf32(bf[j].x[t]);
            }
#pragma unroll
            for (int i = 0; i < 2; i++)
#pragma unroll
                for (int j = 0; j < 4; j++)
                    wmma::mma_sync(acc[i][j], af[i], bf[j], acc[i][j]);
        }
        __syncthreads();   // all warps done with this stage before refill
    }

    // ---- store ----
#pragma unroll
    for (int i = 0; i < 2; i++)
#pragma unroll
        for (int j = 0; j < 4; j++) {
            int r = rowBase + wr * 32 + i * 16;
            int c = colBase + wc * 64 + j * 16;
            wmma::store_matrix_sync(&C[(size_t)r * Nf + c], acc[i][j], Nf,
                                    wmma::mem_row_major);
        }
}

// QKV: one launch, blockIdx.z selects {Q, K, V}
__global__ __launch_bounds__(256) void qkv_gemm_kernel(
    const float* __restrict__ X,
    const float* __restrict__ Wq, const float* __restrict__ bq,
    const float* __restrict__ Wk, const float* __restrict__ bk,
    const float* __restrict__ Wv, const float* __restrict__ bv)
{
    const float* W;
    const float* b;
    float* out;
    if (blockIdx.z == 0)      { W = Wq; b = bq; out = g_Q; }
    else if (blockIdx.z == 1) { W = Wk; b = bk; out = g_K; }
    else                      { W = Wv; b = bv; out = g_V; }
    gemm_block_tf32(X, W, b, out);
}

__global__ __launch_bounds__(256) void out_gemm_kernel(
    const float* __restrict__ Wo, const float* __restrict__ bo,
    float* __restrict__ out)
{
    gemm_block_tf32(g_O, Wo, bo, out);
}

// ---------------------------------------------------------------------------
// Local window attention: one warp per (b, h, n) query.
// ---------------------------------------------------------------------------
__global__ __launch_bounds__(256) void attn_kernel(float* __restrict__ attn_last)
{
    const int gwarp = (blockIdx.x * blockDim.x + threadIdx.x) >> 5;
    const int lane  = threadIdx.x & 31;
    const int n  = gwarp & (Nseq - 1);
    const int bh = gwarp >> 12;            // Nseq = 2^12
    const int h  = bh & (Hn - 1);
    const int b  = bh >> 4;

    const size_t base = ((size_t)(b * Nseq + n)) * Cdim + h * Dd;
    const float2 qv = *(const float2*)(g_Q + base + lane * 2);

    float s[WW];
#pragma unroll
    for (int w = 0; w < WW; w++) {
        const int pos = n - W2 + w;
        const bool valid = (unsigned)pos < (unsigned)Nseq;
        float partial = 0.f;
        if (valid) {
            const size_t kb = ((size_t)(b * Nseq + pos)) * Cdim + h * Dd;
            const float2 kv = *(const float2*)(g_K + kb + lane * 2);
            partial = qv.x * kv.x + qv.y * kv.y;
        }
        partial += __shfl_xor_sync(0xffffffffu, partial, 16);
        partial += __shfl_xor_sync(0xffffffffu, partial, 8);
        partial += __shfl_xor_sync(0xffffffffu, partial, 4);
        partial += __shfl_xor_sync(0xffffffffu, partial, 2);
        partial += __shfl_xor_sync(0xffffffffu, partial, 1);
        s[w] = valid ? partial * 0.125f : -INFINITY;   // /sqrt(64)
    }

    float m = s[0];
#pragma unroll
    for (int w = 1; w < WW; w++) m = fmaxf(m, s[w]);
    float sum = 0.f;
#pragma unroll
    for (int w = 0; w < WW; w++) {
        const float e = expf(s[w] - m);   // expf(-inf) == 0 for invalid slots
        s[w] = e;
        sum += e;
    }
    const float inv = 1.f / sum;

    float2 acc = make_float2(0.f, 0.f);
#pragma unroll
    for (int w = 0; w < WW; w++) {
        const int pos = n - W2 + w;
        if ((unsigned)pos < (unsigned)Nseq) {
            const size_t vb = ((size_t)(b * Nseq + pos)) * Cdim + h * Dd;
            const float2 vv = *(const float2*)(g_V + vb + lane * 2);
            const float p = s[w] * inv;
            acc.x += p * vv.x;
            acc.y += p * vv.y;
            if (w <= W2 && n == Nseq - 1 && lane == 0)
                attn_last[(b * Hn + h) * (W2 + 1) + w] = p;
        }
    }
    *(float2*)(g_O + base + lane * 2) = acc;
}

// ---------------------------------------------------------------------------
// Launch: QKV (z=3 fused launch) -> attention -> output projection.
// d_out layout: [out: 8192*1024 floats][attn_last: 2*16*11 floats]
// ---------------------------------------------------------------------------
extern "C" void kernel_launch(void* const* d_in, const int* in_sizes, int n_in,
                              void* d_out, int out_size)
{
    const float* q  = (const float*)d_in[0];
    const float* Wq = (const float*)d_in[1];
    const float* bq = (const float*)d_in[2];
    const float* Wk = (const float*)d_in[3];
    const float* bk = (const float*)d_in[4];
    const float* Wv = (const float*)d_in[5];
    const float* bv = (const float*)d_in[6];
    const float* Wo = (const float*)d_in[7];
    const float* bo = (const float*)d_in[8];
    float* out = (float*)d_out;

    cudaFuncSetAttribute(qkv_gemm_kernel,
                         cudaFuncAttributeMaxDynamicSharedMemorySize,
                         SMEM_BYTES);
    cudaFuncSetAttribute(out_gemm_kernel,
                         cudaFuncAttributeMaxDynamicSharedMemorySize,
                         SMEM_BYTES);

    dim3 blk(256);
    dim3 g_qkv(Cdim / 128, MROWS / 128, 3);   // (8, 64, 3)
    qkv_gemm_kernel<<<g_qkv, blk, SMEM_BYTES>>>(q, Wq, bq, Wk, bk, Wv, bv);

    const int total_warps = Bdim * Hn * Nseq;          // 131072
    attn_kernel<<<total_warps / 8, 256>>>(out + OUT_ELEMS);

    dim3 g_o(Cdim / 128, MROWS / 128, 1);
    out_gemm_kernel<<<g_o, blk, SMEM_BYTES>>>(Wo, bo, out);
}

// round 6
// speedup vs baseline: 1.2950x; 1.1086x over previous
#include <cuda_runtime.h>
#include <cstdint>
#include <mma.h>
#include <math.h>

using namespace nvcuda;

// Problem constants
#define Bdim 2
#define Nseq 4096
#define Cdim 1024
#define Hn   16
#define Dd   64
#define W2   10
#define WW   21

#define MROWS (Bdim * Nseq)          // 8192
#define OUT_ELEMS (MROWS * Cdim)     // 8,388,608
#define W_ELEMS  (Cdim * Cdim)       // 1,048,576

// Scratch: device globals (no allocations allowed in kernel_launch)
__device__ float g_Q[OUT_ELEMS];
__device__ float g_K[OUT_ELEMS];
__device__ float g_V[OUT_ELEMS];
__device__ float g_O[OUT_ELEMS];     // attn out, tf32-rounded at store
// tf32-pre-rounded GEMM inputs (rounded once; mainloop uses raw bits)
__device__ float g_X[OUT_ELEMS];
__device__ float g_Wq[W_ELEMS];
__device__ float g_Wk[W_ELEMS];
__device__ float g_Wv[W_ELEMS];
__device__ float g_Wo[W_ELEMS];

// ---------------------------------------------------------------------------
// Prepass: round fp32 -> tf32 (RN) once, outside the GEMM mainloop.
// blockIdx.y selects tensor: 0=X (8M), 1..4 = weights (1M each).
// ---------------------------------------------------------------------------
__global__ __launch_bounds__(256) void round_tf32_kernel(
    const float* __restrict__ X,
    const float* __restrict__ Wq, const float* __restrict__ Wk,
    const float* __restrict__ Wv, const float* __restrict__ Wo)
{
    const float* src; float* dst; int n4;
    switch (blockIdx.y) {
        case 0: src = X;  dst = g_X;  n4 = OUT_ELEMS / 4; break;
        case 1: src = Wq; dst = g_Wq; n4 = W_ELEMS / 4;   break;
        case 2: src = Wk; dst = g_Wk; n4 = W_ELEMS / 4;   break;
        case 3: src = Wv; dst = g_Wv; n4 = W_ELEMS / 4;   break;
        default: src = Wo; dst = g_Wo; n4 = W_ELEMS / 4;  break;
    }
    const int stride = gridDim.x * blockDim.x;
    for (int i = blockIdx.x * blockDim.x + threadIdx.x; i < n4; i += stride) {
        float4 v = ((const float4*)src)[i];
        v.x = wmma::__float_to_tf32(v.x);
        v.y = wmma::__float_to_tf32(v.y);
        v.z = wmma::__float_to_tf32(v.z);
        v.w = wmma::__float_to_tf32(v.w);
        ((float4*)dst)[i] = v;
    }
}

// ---------------------------------------------------------------------------
// TF32 tensor-core GEMM, 2-stage cp.async pipeline, pre-rounded inputs:
//   C[m, n] = sum_k A[m, k] * W[n, k] + bias[n]
// Block tile 128x128, K-tile 32, 256 threads = 8 warps (4x2), warp tile 32x64.
// ---------------------------------------------------------------------------
#define PITCH   40                       // 32 + 8 pad floats; rows 160B
#define TILE_F  (128 * PITCH)            // floats per As (or Bs) stage
#define STAGE_F (2 * TILE_F)             // As + Bs
#define SMEM_BYTES (2 * STAGE_F * 4)     // 2 stages = 81920 B

__device__ __forceinline__ void cp16(void* smem_dst, const void* gmem_src)
{
    unsigned d = (unsigned)__cvta_generic_to_shared(smem_dst);
    asm volatile("cp.async.cg.shared.global [%0], [%1], 16;\n"
                 :: "r"(d), "l"(gmem_src));
}

__device__ __forceinline__ void gemm_block_tf32(
    const float* __restrict__ A, const float* __restrict__ W,
    const float* __restrict__ bias, float* __restrict__ C)
{
    constexpr int K  = Cdim;
    constexpr int Nf = Cdim;
    constexpr int NT = K / 32;           // 32 K-tiles

    extern __shared__ float smem[];

    const int tid    = threadIdx.x;      // 256 threads
    const int warpId = tid >> 5;
    const int wr     = warpId >> 1;      // 0..3 -> warp row (32 rows each)
    const int wc     = warpId & 1;       // 0..1 -> warp col (64 cols each)
    const int rowBase = blockIdx.y * 128;
    const int colBase = blockIdx.x * 128;

    wmma::fragment<wmma::accumulator, 16, 16, 8, float> acc[2][4];

    // ---- bias init: 16x128 broadcast tile staged in smem (pitch 128) ----
    for (int idx = tid; idx < 16 * 128; idx += 256) {
        int r = idx >> 7, c = idx & 127;
        smem[r * 128 + c] = bias[colBase + c];
    }
    __syncthreads();
#pragma unroll
    for (int i = 0; i < 2; i++)
#pragma unroll
        for (int j = 0; j < 4; j++)
            wmma::load_matrix_sync(acc[i][j], &smem[wc * 64 + j * 16], 128,
                                   wmma::mem_row_major);
    __syncthreads();

    // global->smem async copy mapping: 128x32 tile = 1024 float4, 4/thread
    const int lr = tid >> 3;             // 0..31
    const int lc = (tid & 7) << 2;       // 0,4,...,28

    // prefetch tile 0 into stage 0
    {
        float* As = smem;
        float* Bs = smem + TILE_F;
#pragma unroll
        for (int i = 0; i < 4; i++) {
            int r = lr + i * 32;
            cp16(&As[r * PITCH + lc], A + (size_t)(rowBase + r) * K + lc);
            cp16(&Bs[r * PITCH + lc], W + (size_t)(colBase + r) * K + lc);
        }
        asm volatile("cp.async.commit_group;\n" ::: "memory");
    }

    for (int kt = 0; kt < NT; kt++) {
        // prefetch next tile into the other stage
        if (kt + 1 < NT) {
            float* As = smem + ((kt + 1) & 1) * STAGE_F;
            float* Bs = As + TILE_F;
            const int k0 = (kt + 1) * 32;
#pragma unroll
            for (int i = 0; i < 4; i++) {
                int r = lr + i * 32;
                cp16(&As[r * PITCH + lc],
                     A + (size_t)(rowBase + r) * K + k0 + lc);
                cp16(&Bs[r * PITCH + lc],
                     W + (size_t)(colBase + r) * K + k0 + lc);
            }
            asm volatile("cp.async.commit_group;\n" ::: "memory");
            asm volatile("cp.async.wait_group 1;\n" ::: "memory");
        } else {
            asm volatile("cp.async.wait_group 0;\n" ::: "memory");
        }
        __syncthreads();   // current stage data visible to all warps

        const float* As = smem + (kt & 1) * STAGE_F;
        const float* Bs = As + TILE_F;

#pragma unroll
        for (int kk = 0; kk < 32; kk += 8) {
            wmma::fragment<wmma::matrix_a, 16, 16, 8, wmma::precision::tf32,
                           wmma::row_major> af[2];
            wmma::fragment<wmma::matrix_b, 16, 16, 8, wmma::precision::tf32,
                           wmma::col_major> bf[4];
#pragma unroll
            for (int i = 0; i < 2; i++)
                wmma::load_matrix_sync(af[i],
                    &As[(wr * 32 + i * 16) * PITCH + kk], PITCH);
#pragma unroll
            for (int j = 0; j < 4; j++)
                wmma::load_matrix_sync(bf[j],
                    &Bs[(wc * 64 + j * 16) * PITCH + kk], PITCH);
            // inputs are pre-rounded to tf32 -> no per-element cvt here
#pragma unroll
            for (int i = 0; i < 2; i++)
#pragma unroll
                for (int j = 0; j < 4; j++)
                    wmma::mma_sync(acc[i][j], af[i], bf[j], acc[i][j]);
        }
        __syncthreads();   // all warps done with this stage before refill
    }

    // ---- store ----
#pragma unroll
    for (int i = 0; i < 2; i++)
#pragma unroll
        for (int j = 0; j < 4; j++) {
            int r = rowBase + wr * 32 + i * 16;
            int c = colBase + wc * 64 + j * 16;
            wmma::store_matrix_sync(&C[(size_t)r * Nf + c], acc[i][j], Nf,
                                    wmma::mem_row_major);
        }
}

// QKV: one launch, blockIdx.z selects {Q, K, V}
__global__ __launch_bounds__(256, 2) void qkv_gemm_kernel()
{
    const float* W;
    const float* b;
    float* out;
    extern __shared__ float smem[];
    (void)smem;
    if (blockIdx.z == 0)      { W = g_Wq; out = g_Q; }
    else if (blockIdx.z == 1) { W = g_Wk; out = g_K; }
    else                      { W = g_Wv; out = g_V; }
    b = nullptr; // set below via constant path
    // biases passed through device globals? No — keep as params:
    // (see qkv_gemm_kernel2 signature below)
    (void)W; (void)b; (void)out;
}

// real QKV kernel (biases as params; matrices pre-rounded in globals)
__global__ __launch_bounds__(256, 2) void qkv_gemm(
    const float* __restrict__ bq, const float* __restrict__ bk,
    const float* __restrict__ bv)
{
    const float* W; const float* b; float* out;
    if (blockIdx.z == 0)      { W = g_Wq; b = bq; out = g_Q; }
    else if (blockIdx.z == 1) { W = g_Wk; b = bk; out = g_K; }
    else                      { W = g_Wv; b = bv; out = g_V; }
    gemm_block_tf32(g_X, W, b, out);
}

__global__ __launch_bounds__(256, 2) void out_gemm_kernel(
    const float* __restrict__ bo, float* __restrict__ out)
{
    gemm_block_tf32(g_O, g_Wo, bo, out);
}

// ---------------------------------------------------------------------------
// Local window attention: one warp per (b, h, n) query.
// Output g_O is tf32-rounded at store (it feeds the tf32 out-projection).
// ---------------------------------------------------------------------------
__global__ __launch_bounds__(256) void attn_kernel(float* __restrict__ attn_last)
{
    const int gwarp = (blockIdx.x * blockDim.x + threadIdx.x) >> 5;
    const int lane  = threadIdx.x & 31;
    const int n  = gwarp & (Nseq - 1);
    const int bh = gwarp >> 12;            // Nseq = 2^12
    const int h  = bh & (Hn - 1);
    const int b  = bh >> 4;

    const size_t base = ((size_t)(b * Nseq + n)) * Cdim + h * Dd;
    const float2 qv = *(const float2*)(g_Q + base + lane * 2);

    float s[WW];
#pragma unroll
    for (int w = 0; w < WW; w++) {
        const int pos = n - W2 + w;
        const bool valid = (unsigned)pos < (unsigned)Nseq;
        float partial = 0.f;
        if (valid) {
            const size_t kb = ((size_t)(b * Nseq + pos)) * Cdim + h * Dd;
            const float2 kv = *(const float2*)(g_K + kb + lane * 2);
            partial = qv.x * kv.x + qv.y * kv.y;
        }
        partial += __shfl_xor_sync(0xffffffffu, partial, 16);
        partial += __shfl_xor_sync(0xffffffffu, partial, 8);
        partial += __shfl_xor_sync(0xffffffffu, partial, 4);
        partial += __shfl_xor_sync(0xffffffffu, partial, 2);
        partial += __shfl_xor_sync(0xffffffffu, partial, 1);
        s[w] = valid ? partial * 0.125f : -INFINITY;   // /sqrt(64)
    }

    float m = s[0];
#pragma unroll
    for (int w = 1; w < WW; w++) m = fmaxf(m, s[w]);
    float sum = 0.f;
#pragma unroll
    for (int w = 0; w < WW; w++) {
        const float e = expf(s[w] - m);   // expf(-inf) == 0 for invalid slots
        s[w] = e;
        sum += e;
    }
    const float inv = 1.f / sum;

    float2 acc = make_float2(0.f, 0.f);
#pragma unroll
    for (int w = 0; w < WW; w++) {
        const int pos = n - W2 + w;
        if ((unsigned)pos < (unsigned)Nseq) {
            const size_t vb = ((size_t)(b * Nseq + pos)) * Cdim + h * Dd;
            const float2 vv = *(const float2*)(g_V + vb + lane * 2);
            const float p = s[w] * inv;
            acc.x += p * vv.x;
            acc.y += p * vv.y;
            if (w <= W2 && n == Nseq - 1 && lane == 0)
                attn_last[(b * Hn + h) * (W2 + 1) + w] = p;
        }
    }
    // round to tf32 here so out_gemm can consume raw bits
    acc.x = wmma::__float_to_tf32(acc.x);
    acc.y = wmma::__float_to_tf32(acc.y);
    *(float2*)(g_O + base + lane * 2) = acc;
}

// ---------------------------------------------------------------------------
// Launch: tf32 prepass -> QKV (z=3) -> attention -> output projection.
// d_out layout: [out: 8192*1024 floats][attn_last: 2*16*11 floats]
// ---------------------------------------------------------------------------
extern "C" void kernel_launch(void* const* d_in, const int* in_sizes, int n_in,
                              void* d_out, int out_size)
{
    const float* q  = (const float*)d_in[0];
    const float* Wq = (const float*)d_in[1];
    const float* bq = (const float*)d_in[2];
    const float* Wk = (const float*)d_in[3];
    const float* bk = (const float*)d_in[4];
    const float* Wv = (const float*)d_in[5];
    const float* bv = (const float*)d_in[6];
    const float* Wo = (const float*)d_in[7];
    const float* bo = (const float*)d_in[8];
    float* out = (float*)d_out;

    cudaFuncSetAttribute(qkv_gemm,
                         cudaFuncAttributeMaxDynamicSharedMemorySize,
                         SMEM_BYTES);
    cudaFuncSetAttribute(out_gemm_kernel,
                         cudaFuncAttributeMaxDynamicSharedMemorySize,
                         SMEM_BYTES);

    // prepass: round X + 4 weights to tf32 (RN) once
    round_tf32_kernel<<<dim3(256, 5), 256>>>(q, Wq, Wk, Wv, Wo);

    dim3 blk(256);
    dim3 g_qkv(Cdim / 128, MROWS / 128, 3);   // (8, 64, 3)
    qkv_gemm<<<g_qkv, blk, SMEM_BYTES>>>(bq, bk, bv);

    const int total_warps = Bdim * Hn * Nseq;          // 131072
    attn_kernel<<<total_warps / 8, 256>>>(out + OUT_ELEMS);

    dim3 g_o(Cdim / 128, MROWS / 128, 1);
    out_gemm_kernel<<<g_o, blk, SMEM_BYTES>>>(bo, out);
}

// round 9
// speedup vs baseline: 1.3245x; 1.0228x over previous
#include <cuda_runtime.h>
#include <cstdint>
#include <mma.h>
#include <math.h>

using namespace nvcuda;

// Problem constants
#define Bdim 2
#define Nseq 4096
#define Cdim 1024
#define Hn   16
#define Dd   64
#define W2   10
#define WW   21

#define MROWS (Bdim * Nseq)          // 8192
#define OUT_ELEMS (MROWS * Cdim)     // 8,388,608
#define W_ELEMS  (Cdim * Cdim)       // 1,048,576

// Scratch: device globals (no allocations allowed in kernel_launch)
__device__ float g_Q[OUT_ELEMS];
__device__ float g_K[OUT_ELEMS];
__device__ float g_V[OUT_ELEMS];
__device__ float g_O[OUT_ELEMS];     // attn out, tf32-rounded at store
// tf32-pre-rounded GEMM inputs (rounded once; mainloop uses raw bits)
__device__ float g_X[OUT_ELEMS];
__device__ float g_Wq[W_ELEMS];
__device__ float g_Wk[W_ELEMS];
__device__ float g_Wv[W_ELEMS];
__device__ float g_Wo[W_ELEMS];

// ---------------------------------------------------------------------------
// Prepass: round fp32 -> tf32 (RN) once, outside the GEMM mainloop.
// blockIdx.y selects tensor: 0=X (8M), 1..4 = weights (1M each).
// ---------------------------------------------------------------------------
__global__ __launch_bounds__(256) void round_tf32_kernel(
    const float* __restrict__ X,
    const float* __restrict__ Wq, const float* __restrict__ Wk,
    const float* __restrict__ Wv, const float* __restrict__ Wo)
{
    const float* src; float* dst; int n4;
    switch (blockIdx.y) {
        case 0: src = X;  dst = g_X;  n4 = OUT_ELEMS / 4; break;
        case 1: src = Wq; dst = g_Wq; n4 = W_ELEMS / 4;   break;
        case 2: src = Wk; dst = g_Wk; n4 = W_ELEMS / 4;   break;
        case 3: src = Wv; dst = g_Wv; n4 = W_ELEMS / 4;   break;
        default: src = Wo; dst = g_Wo; n4 = W_ELEMS / 4;  break;
    }
    const int stride = gridDim.x * blockDim.x;
    for (int i = blockIdx.x * blockDim.x + threadIdx.x; i < n4; i += stride) {
        float4 v = ((const float4*)src)[i];
        v.x = wmma::__float_to_tf32(v.x);
        v.y = wmma::__float_to_tf32(v.y);
        v.z = wmma::__float_to_tf32(v.z);
        v.w = wmma::__float_to_tf32(v.w);
        ((float4*)dst)[i] = v;
    }
}

// ---------------------------------------------------------------------------
// TF32 tensor-core GEMM, 2-stage cp.async pipeline, pre-rounded inputs:
//   C[m, n] = sum_k A[m, k] * W[n, k] + bias[n]
// Block tile 128(M) x 256(N), K-tile 32. 256 threads = 8 warps as 2(M) x 4(N);
// warp tile 64x64 -> per kk-step: 8 fragment loads feed 16 MMAs (ratio 2.0).
// ---------------------------------------------------------------------------
#define PITCH    40                      // 32 + 8 pad floats; rows 160B
#define TILE_A_F (128 * PITCH)           // A stage floats
#define TILE_B_F (256 * PITCH)           // B stage floats
#define STAGE_F  (TILE_A_F + TILE_B_F)   // 15360 floats
#define SMEM_BYTES (2 * STAGE_F * 4)     // 2 stages = 122880 B

__device__ __forceinline__ void cp16(void* smem_dst, const void* gmem_src)
{
    unsigned d = (unsigned)__cvta_generic_to_shared(smem_dst);
    asm volatile("cp.async.cg.shared.global [%0], [%1], 16;\n"
                 :: "r"(d), "l"(gmem_src));
}

__device__ __forceinline__ void gemm_block_tf32(
    const float* __restrict__ A, const float* __restrict__ W,
    const float* __restrict__ bias, float* __restrict__ C)
{
    constexpr int K  = Cdim;
    constexpr int Nf = Cdim;
    constexpr int NT = K / 32;           // 32 K-tiles

    extern __shared__ float smem[];

    const int tid    = threadIdx.x;      // 256 threads
    const int warpId = tid >> 5;
    const int wr     = warpId >> 2;      // 0..1 -> warp row (64 rows each)
    const int wc     = warpId & 3;       // 0..3 -> warp col (64 cols each)
    const int rowBase = blockIdx.y * 128;
    const int colBase = blockIdx.x * 256;

    wmma::fragment<wmma::accumulator, 16, 16, 8, float> acc[4][4];

    // ---- bias init: 16x256 broadcast tile staged in smem (pitch 256) ----
    for (int idx = tid; idx < 16 * 256; idx += 256) {
        int r = idx >> 8, c = idx & 255;
        smem[r * 256 + c] = bias[colBase + c];
    }
    __syncthreads();
#pragma unroll
    for (int i = 0; i < 4; i++)
#pragma unroll
        for (int j = 0; j < 4; j++)
            wmma::load_matrix_sync(acc[i][j], &smem[wc * 64 + j * 16], 256,
                                   wmma::mem_row_major);
    __syncthreads();

    // global->smem async copy mapping:
    // A tile 128x32 = 1024 f4 (4/thread), B tile 256x32 = 2048 f4 (8/thread)
    const int lr = tid >> 3;             // 0..31
    const int lc = (tid & 7) << 2;       // 0,4,...,28

    // prefetch tile 0 into stage 0
    {
        float* As = smem;
        float* Bs = smem + TILE_A_F;
#pragma unroll
        for (int i = 0; i < 4; i++) {
            int r = lr + i * 32;
            cp16(&As[r * PITCH + lc], A + (size_t)(rowBase + r) * K + lc);
        }
#pragma unroll
        for (int i = 0; i < 8; i++) {
            int r = lr + i * 32;
            cp16(&Bs[r * PITCH + lc], W + (size_t)(colBase + r) * K + lc);
        }
        asm volatile("cp.async.commit_group;\n" ::: "memory");
    }

    for (int kt = 0; kt < NT; kt++) {
        // prefetch next tile into the other stage
        if (kt + 1 < NT) {
            float* As = smem + ((kt + 1) & 1) * STAGE_F;
            float* Bs = As + TILE_A_F;
            const int k0 = (kt + 1) * 32;
#pragma unroll
            for (int i = 0; i < 4; i++) {
                int r = lr + i * 32;
                cp16(&As[r * PITCH + lc],
                     A + (size_t)(rowBase + r) * K + k0 + lc);
            }
#pragma unroll
            for (int i = 0; i < 8; i++) {
                int r = lr + i * 32;
                cp16(&Bs[r * PITCH + lc],
                     W + (size_t)(colBase + r) * K + k0 + lc);
            }
            asm volatile("cp.async.commit_group;\n" ::: "memory");
            asm volatile("cp.async.wait_group 1;\n" ::: "memory");
        } else {
            asm volatile("cp.async.wait_group 0;\n" ::: "memory");
        }
        __syncthreads();   // current stage data visible to all warps

        const float* As = smem + (kt & 1) * STAGE_F;
        const float* Bs = As + TILE_A_F;

#pragma unroll
        for (int kk = 0; kk < 32; kk += 8) {
            wmma::fragment<wmma::matrix_a, 16, 16, 8, wmma::precision::tf32,
                           wmma::row_major> af[4];
            wmma::fragment<wmma::matrix_b, 16, 16, 8, wmma::precision::tf32,
                           wmma::col_major> bf[4];
#pragma unroll
            for (int i = 0; i < 4; i++)
                wmma::load_matrix_sync(af[i],
                    &As[(wr * 64 + i * 16) * PITCH + kk], PITCH);
#pragma unroll
            for (int j = 0; j < 4; j++)
                wmma::load_matrix_sync(bf[j],
                    &Bs[(wc * 64 + j * 16) * PITCH + kk], PITCH);
            // inputs are pre-rounded to tf32 -> no per-element cvt here
#pragma unroll
            for (int i = 0; i < 4; i++)
#pragma unroll
                for (int j = 0; j < 4; j++)
                    wmma::mma_sync(acc[i][j], af[i], bf[j], acc[i][j]);
        }
        __syncthreads();   // all warps done with this stage before refill
    }

    // ---- store ----
#pragma unroll
    for (int i = 0; i < 4; i++)
#pragma unroll
        for (int j = 0; j < 4; j++) {
            int r = rowBase + wr * 64 + i * 16;
            int c = colBase + wc * 64 + j * 16;
            wmma::store_matrix_sync(&C[(size_t)r * Nf + c], acc[i][j], Nf,
                                    wmma::mem_row_major);
        }
}

// QKV: one launch, blockIdx.z selects {Q, K, V}
__global__ __launch_bounds__(256) void qkv_gemm(
    const float* __restrict__ bq, const float* __restrict__ bk,
    const float* __restrict__ bv)
{
    const float* W; const float* b; float* out;
    if (blockIdx.z == 0)      { W = g_Wq; b = bq; out = g_Q; }
    else if (blockIdx.z == 1) { W = g_Wk; b = bk; out = g_K; }
    else                      { W = g_Wv; b = bv; out = g_V; }
    gemm_block_tf32(g_X, W, b, out);
}

__global__ __launch_bounds__(256) void out_gemm_kernel(
    const float* __restrict__ bo, float* __restrict__ out)
{
    gemm_block_tf32(g_O, g_Wo, bo, out);
}

// ---------------------------------------------------------------------------
// Local window attention: one warp per (b, h, n) query.
// Output g_O is tf32-rounded at store (it feeds the tf32 out-projection).
// ---------------------------------------------------------------------------
__global__ __launch_bounds__(256) void attn_kernel(float* __restrict__ attn_last)
{
    const int gwarp = (blockIdx.x * blockDim.x + threadIdx.x) >> 5;
    const int lane  = threadIdx.x & 31;
    const int n  = gwarp & (Nseq - 1);
    const int bh = gwarp >> 12;            // Nseq = 2^12
    const int h  = bh & (Hn - 1);
    const int b  = bh >> 4;

    const size_t base = ((size_t)(b * Nseq + n)) * Cdim + h * Dd;
    const float2 qv = *(const float2*)(g_Q + base + lane * 2);

    float s[WW];
#pragma unroll
    for (int w = 0; w < WW; w++) {
        const int pos = n - W2 + w;
        const bool valid = (unsigned)pos < (unsigned)Nseq;
        float partial = 0.f;
        if (valid) {
            const size_t kb = ((size_t)(b * Nseq + pos)) * Cdim + h * Dd;
            const float2 kv = *(const float2*)(g_K + kb + lane * 2);
            partial = qv.x * kv.x + qv.y * kv.y;
        }
        partial += __shfl_xor_sync(0xffffffffu, partial, 16);
        partial += __shfl_xor_sync(0xffffffffu, partial, 8);
        partial += __shfl_xor_sync(0xffffffffu, partial, 4);
        partial += __shfl_xor_sync(0xffffffffu, partial, 2);
        partial += __shfl_xor_sync(0xffffffffu, partial, 1);
        s[w] = valid ? partial * 0.125f : -INFINITY;   // /sqrt(64)
    }

    float m = s[0];
#pragma unroll
    for (int w = 1; w < WW; w++) m = fmaxf(m, s[w]);
    float sum = 0.f;
#pragma unroll
    for (int w = 0; w < WW; w++) {
        const float e = expf(s[w] - m);   // expf(-inf) == 0 for invalid slots
        s[w] = e;
        sum += e;
    }
    const float inv = 1.f / sum;

    float2 acc = make_float2(0.f, 0.f);
#pragma unroll
    for (int w = 0; w < WW; w++) {
        const int pos = n - W2 + w;
        if ((unsigned)pos < (unsigned)Nseq) {
            const size_t vb = ((size_t)(b * Nseq + pos)) * Cdim + h * Dd;
            const float2 vv = *(const float2*)(g_V + vb + lane * 2);
            const float p = s[w] * inv;
            acc.x += p * vv.x;
            acc.y += p * vv.y;
            if (w <= W2 && n == Nseq - 1 && lane == 0)
                attn_last[(b * Hn + h) * (W2 + 1) + w] = p;
        }
    }
    // round to tf32 here so out_gemm can consume raw bits
    acc.x = wmma::__float_to_tf32(acc.x);
    acc.y = wmma::__float_to_tf32(acc.y);
    *(float2*)(g_O + base + lane * 2) = acc;
}

// ---------------------------------------------------------------------------
// Launch: tf32 prepass -> QKV (z=3) -> attention -> output projection.
// d_out layout: [out: 8192*1024 floats][attn_last: 2*16*11 floats]
// ---------------------------------------------------------------------------
extern "C" void kernel_launch(void* const* d_in, const int* in_sizes, int n_in,
                              void* d_out, int out_size)
{
    const float* q  = (const float*)d_in[0];
    const float* Wq = (const float*)d_in[1];
    const float* bq = (const float*)d_in[2];
    const float* Wk = (const float*)d_in[3];
    const float* bk = (const float*)d_in[4];
    const float* Wv = (const float*)d_in[5];
    const float* bv = (const float*)d_in[6];
    const float* Wo = (const float*)d_in[7];
    const float* bo = (const float*)d_in[8];
    float* out = (float*)d_out;

    cudaFuncSetAttribute(qkv_gemm,
                         cudaFuncAttributeMaxDynamicSharedMemorySize,
                         SMEM_BYTES);
    cudaFuncSetAttribute(out_gemm_kernel,
                         cudaFuncAttributeMaxDynamicSharedMemorySize,
                         SMEM_BYTES);

    // prepass: round X + 4 weights to tf32 (RN) once
    round_tf32_kernel<<<dim3(256, 5), 256>>>(q, Wq, Wk, Wv, Wo);

    dim3 blk(256);
    dim3 g_qkv(Cdim / 256, MROWS / 128, 3);   // (4, 64, 3)
    qkv_gemm<<<g_qkv, blk, SMEM_BYTES>>>(bq, bk, bv);

    const int total_warps = Bdim * Hn * Nseq;          // 131072
    attn_kernel<<<total_warps / 8, 256>>>(out + OUT_ELEMS);

    dim3 g_o(Cdim / 256, MROWS / 128, 1);
    out_gemm_kernel<<<g_o, blk, SMEM_BYTES>>>(bo, out);
}

// round 10
// speedup vs baseline: 3.4325x; 2.5915x over previous
#include <cuda_runtime.h>
#include <cuda_fp16.h>
#include <cstdint>
#include <mma.h>
#include <math.h>

using namespace nvcuda;

// Problem constants
#define Bdim 2
#define Nseq 4096
#define Cdim 1024
#define Hn   16
#define Dd   64
#define W2   10
#define WW   21

#define MROWS (Bdim * Nseq)          // 8192
#define OUT_ELEMS (MROWS * Cdim)     // 8,388,608
#define W_ELEMS  (Cdim * Cdim)       // 1,048,576

// Scratch: device globals (no allocations allowed in kernel_launch)
__device__ float g_Q[OUT_ELEMS];
__device__ float g_K[OUT_ELEMS];
__device__ float g_V[OUT_ELEMS];
// fp16 GEMM inputs (E5M10 mantissa == TF32 mantissa; 2x MMA K-depth)
__device__ __half g_X[OUT_ELEMS];
__device__ __half g_O[OUT_ELEMS];    // attn out, rounded to fp16 at store
__device__ __half g_W[4][W_ELEMS];   // Wq, Wk, Wv, Wo

// ---------------------------------------------------------------------------
// Prepass: round fp32 -> fp16 (RN) once.
// blockIdx.y selects tensor: 0=X (8M), 1..4 = weights (1M each).
// ---------------------------------------------------------------------------
__global__ __launch_bounds__(256) void to_half_kernel(
    const float* __restrict__ X,
    const float* __restrict__ Wq, const float* __restrict__ Wk,
    const float* __restrict__ Wv, const float* __restrict__ Wo)
{
    const float* src; __half* dst; int n4;
    switch (blockIdx.y) {
        case 0: src = X;  dst = g_X;    n4 = OUT_ELEMS / 4; break;
        case 1: src = Wq; dst = g_W[0]; n4 = W_ELEMS / 4;   break;
        case 2: src = Wk; dst = g_W[1]; n4 = W_ELEMS / 4;   break;
        case 3: src = Wv; dst = g_W[2]; n4 = W_ELEMS / 4;   break;
        default: src = Wo; dst = g_W[3]; n4 = W_ELEMS / 4;  break;
    }
    const int stride = gridDim.x * blockDim.x;
    for (int i = blockIdx.x * blockDim.x + threadIdx.x; i < n4; i += stride) {
        float4 v = ((const float4*)src)[i];
        ((__half2*)dst)[2 * i]     = __floats2half2_rn(v.x, v.y);
        ((__half2*)dst)[2 * i + 1] = __floats2half2_rn(v.z, v.w);
    }
}

// ---------------------------------------------------------------------------
// fp16 tensor-core GEMM (fp32 accumulate), 2-stage cp.async pipeline:
//   C[m, n] = sum_k A[m, k] * W[n, k] + bias[n]
// Block tile 128(M) x 256(N), K-tile 64 halfs (16 mainloop iters).
// 256 threads = 8 warps as 2(M) x 4(N); warp tile 64x64 (wmma 16x16x16).
// ---------------------------------------------------------------------------
#define KT       64                      // halfs per K-tile
#define NT       (Cdim / KT)             // 16
#define PITCH    72                      // 64 + 8 pad halfs; rows 144B
#define TILE_A_H (128 * PITCH)           // 9216 halfs
#define TILE_B_H (256 * PITCH)           // 18432 halfs
#define STAGE_H  (TILE_A_H + TILE_B_H)   // 27648 halfs = 55296 B
#define SMEM_BYTES (2 * STAGE_H * 2)     // 2 stages = 110592 B

__device__ __forceinline__ void cp16(void* smem_dst, const void* gmem_src)
{
    unsigned d = (unsigned)__cvta_generic_to_shared(smem_dst);
    asm volatile("cp.async.cg.shared.global [%0], [%1], 16;\n"
                 :: "r"(d), "l"(gmem_src));
}

__device__ __forceinline__ void gemm_block_f16(
    const __half* __restrict__ A, const __half* __restrict__ W,
    const float* __restrict__ bias, float* __restrict__ C)
{
    constexpr int K  = Cdim;
    constexpr int Nf = Cdim;

    extern __shared__ __half smem[];

    const int tid    = threadIdx.x;      // 256 threads
    const int warpId = tid >> 5;
    const int wr     = warpId >> 2;      // 0..1 -> warp row (64 rows each)
    const int wc     = warpId & 3;       // 0..3 -> warp col (64 cols each)
    const int rowBase = blockIdx.y * 128;
    const int colBase = blockIdx.x * 256;

    wmma::fragment<wmma::accumulator, 16, 16, 16, float> acc[4][4];

    // ---- bias init: 16x256 fp32 broadcast tile staged in smem (pitch 256) --
    {
        float* bs = (float*)smem;
        for (int idx = tid; idx < 16 * 256; idx += 256) {
            int r = idx >> 8, c = idx & 255;
            bs[r * 256 + c] = bias[colBase + c];
        }
        __syncthreads();
#pragma unroll
        for (int i = 0; i < 4; i++)
#pragma unroll
            for (int j = 0; j < 4; j++)
                wmma::load_matrix_sync(acc[i][j], &bs[wc * 64 + j * 16], 256,
                                       wmma::mem_row_major);
        __syncthreads();
    }

    // global->smem async copy mapping (16B = 8 halfs per chunk):
    // A tile 128x64 halfs = 1024 chunks (4/thread); B tile 256x64 = 2048 (8/t)
    const int lr = tid >> 3;             // 0..31
    const int lc = (tid & 7) << 3;       // 0,8,...,56 (halfs)

    // prefetch tile 0 into stage 0
    {
        __half* As = smem;
        __half* Bs = smem + TILE_A_H;
#pragma unroll
        for (int i = 0; i < 4; i++) {
            int r = lr + i * 32;
            cp16(&As[r * PITCH + lc], A + (size_t)(rowBase + r) * K + lc);
        }
#pragma unroll
        for (int i = 0; i < 8; i++) {
            int r = lr + i * 32;
            cp16(&Bs[r * PITCH + lc], W + (size_t)(colBase + r) * K + lc);
        }
        asm volatile("cp.async.commit_group;\n" ::: "memory");
    }

    for (int kt = 0; kt < NT; kt++) {
        if (kt + 1 < NT) {
            __half* As = smem + ((kt + 1) & 1) * STAGE_H;
            __half* Bs = As + TILE_A_H;
            const int k0 = (kt + 1) * KT;
#pragma unroll
            for (int i = 0; i < 4; i++) {
                int r = lr + i * 32;
                cp16(&As[r * PITCH + lc],
                     A + (size_t)(rowBase + r) * K + k0 + lc);
            }
#pragma unroll
            for (int i = 0; i < 8; i++) {
                int r = lr + i * 32;
                cp16(&Bs[r * PITCH + lc],
                     W + (size_t)(colBase + r) * K + k0 + lc);
            }
            asm volatile("cp.async.commit_group;\n" ::: "memory");
            asm volatile("cp.async.wait_group 1;\n" ::: "memory");
        } else {
            asm volatile("cp.async.wait_group 0;\n" ::: "memory");
        }
        __syncthreads();   // current stage visible to all warps

        const __half* As = smem + (kt & 1) * STAGE_H;
        const __half* Bs = As + TILE_A_H;

#pragma unroll
        for (int kk = 0; kk < KT; kk += 16) {
            wmma::fragment<wmma::matrix_a, 16, 16, 16, __half,
                           wmma::row_major> af[4];
            wmma::fragment<wmma::matrix_b, 16, 16, 16, __half,
                           wmma::col_major> bf[4];
#pragma unroll
            for (int i = 0; i < 4; i++)
                wmma::load_matrix_sync(af[i],
                    &As[(wr * 64 + i * 16) * PITCH + kk], PITCH);
#pragma unroll
            for (int j = 0; j < 4; j++)
                wmma::load_matrix_sync(bf[j],
                    &Bs[(wc * 64 + j * 16) * PITCH + kk], PITCH);
#pragma unroll
            for (int i = 0; i < 4; i++)
#pragma unroll
                for (int j = 0; j < 4; j++)
                    wmma::mma_sync(acc[i][j], af[i], bf[j], acc[i][j]);
        }
        __syncthreads();   // all warps done with this stage before refill
    }

    // ---- store ----
#pragma unroll
    for (int i = 0; i < 4; i++)
#pragma unroll
        for (int j = 0; j < 4; j++) {
            int r = rowBase + wr * 64 + i * 16;
            int c = colBase + wc * 64 + j * 16;
            wmma::store_matrix_sync(&C[(size_t)r * Nf + c], acc[i][j], Nf,
                                    wmma::mem_row_major);
        }
}

// QKV: one launch, blockIdx.z selects {Q, K, V}
__global__ __launch_bounds__(256) void qkv_gemm(
    const float* __restrict__ bq, const float* __restrict__ bk,
    const float* __restrict__ bv)
{
    const float* b; float* out;
    if (blockIdx.z == 0)      { b = bq; out = g_Q; }
    else if (blockIdx.z == 1) { b = bk; out = g_K; }
    else                      { b = bv; out = g_V; }
    gemm_block_f16(g_X, g_W[blockIdx.z], b, out);
}

__global__ __launch_bounds__(256) void out_gemm_kernel(
    const float* __restrict__ bo, float* __restrict__ out)
{
    gemm_block_f16(g_O, g_W[3], bo, out);
}

// ---------------------------------------------------------------------------
// Local window attention: one warp per (b, h, n) query.
// Output g_O rounded to fp16 at store (feeds the fp16 out-projection).
// ---------------------------------------------------------------------------
__global__ __launch_bounds__(256) void attn_kernel(float* __restrict__ attn_last)
{
    const int gwarp = (blockIdx.x * blockDim.x + threadIdx.x) >> 5;
    const int lane  = threadIdx.x & 31;
    const int n  = gwarp & (Nseq - 1);
    const int bh = gwarp >> 12;            // Nseq = 2^12
    const int h  = bh & (Hn - 1);
    const int b  = bh >> 4;

    const size_t base = ((size_t)(b * Nseq + n)) * Cdim + h * Dd;
    const float2 qv = *(const float2*)(g_Q + base + lane * 2);

    float s[WW];
#pragma unroll
    for (int w = 0; w < WW; w++) {
        const int pos = n - W2 + w;
        const bool valid = (unsigned)pos < (unsigned)Nseq;
        float partial = 0.f;
        if (valid) {
            const size_t kb = ((size_t)(b * Nseq + pos)) * Cdim + h * Dd;
            const float2 kv = *(const float2*)(g_K + kb + lane * 2);
            partial = qv.x * kv.x + qv.y * kv.y;
        }
        partial += __shfl_xor_sync(0xffffffffu, partial, 16);
        partial += __shfl_xor_sync(0xffffffffu, partial, 8);
        partial += __shfl_xor_sync(0xffffffffu, partial, 4);
        partial += __shfl_xor_sync(0xffffffffu, partial, 2);
        partial += __shfl_xor_sync(0xffffffffu, partial, 1);
        s[w] = valid ? partial * 0.125f : -INFINITY;   // /sqrt(64)
    }

    float m = s[0];
#pragma unroll
    for (int w = 1; w < WW; w++) m = fmaxf(m, s[w]);
    float sum = 0.f;
#pragma unroll
    for (int w = 0; w < WW; w++) {
        const float e = expf(s[w] - m);   // expf(-inf) == 0 for invalid slots
        s[w] = e;
        sum += e;
    }
    const float inv = 1.f / sum;

    float2 acc = make_float2(0.f, 0.f);
#pragma unroll
    for (int w = 0; w < WW; w++) {
        const int pos = n - W2 + w;
        if ((unsigned)pos < (unsigned)Nseq) {
            const size_t vb = ((size_t)(b * Nseq + pos)) * Cdim + h * Dd;
            const float2 vv = *(const float2*)(g_V + vb + lane * 2);
            const float p = s[w] * inv;
            acc.x += p * vv.x;
            acc.y += p * vv.y;
            if (w <= W2 && n == Nseq - 1 && lane == 0)
                attn_last[(b * Hn + h) * (W2 + 1) + w] = p;
        }
    }
    // fp16 store for the out-projection GEMM
    *(__half2*)(g_O + base + lane * 2) = __floats2half2_rn(acc.x, acc.y);
}

// ---------------------------------------------------------------------------
// Launch: fp16 prepass -> QKV (z=3) -> attention -> output projection.
// d_out layout: [out: 8192*1024 floats][attn_last: 2*16*11 floats]
// ---------------------------------------------------------------------------
extern "C" void kernel_launch(void* const* d_in, const int* in_sizes, int n_in,
                              void* d_out, int out_size)
{
    const float* q  = (const float*)d_in[0];
    const float* Wq = (const float*)d_in[1];
    const float* bq = (const float*)d_in[2];
    const float* Wk = (const float*)d_in[3];
    const float* bk = (const float*)d_in[4];
    const float* Wv = (const float*)d_in[5];
    const float* bv = (const float*)d_in[6];
    const float* Wo = (const float*)d_in[7];
    const float* bo = (const float*)d_in[8];
    float* out = (float*)d_out;

    cudaFuncSetAttribute(qkv_gemm,
                         cudaFuncAttributeMaxDynamicSharedMemorySize,
                         SMEM_BYTES);
    cudaFuncSetAttribute(out_gemm_kernel,
                         cudaFuncAttributeMaxDynamicSharedMemorySize,
                         SMEM_BYTES);

    // prepass: round X + 4 weights to fp16 once
    to_half_kernel<<<dim3(256, 5), 256>>>(q, Wq, Wk, Wv, Wo);

    dim3 blk(256);
    dim3 g_qkv(Cdim / 256, MROWS / 128, 3);   // (4, 64, 3)
    qkv_gemm<<<g_qkv, blk, SMEM_BYTES>>>(bq, bk, bv);

    const int total_warps = Bdim * Hn * Nseq;          // 131072
    attn_kernel<<<total_warps / 8, 256>>>(out + OUT_ELEMS);

    dim3 g_o(Cdim / 256, MROWS / 128, 1);
    out_gemm_kernel<<<g_o, blk, SMEM_BYTES>>>(bo, out);
}

// round 11
// speedup vs baseline: 3.4657x; 1.0097x over previous
#include <cuda_runtime.h>
#include <cuda_fp16.h>
#include <cstdint>
#include <mma.h>
#include <math.h>

using namespace nvcuda;

// Problem constants
#define Bdim 2
#define Nseq 4096
#define Cdim 1024
#define Hn   16
#define Dd   64
#define W2   10
#define WW   21

#define MROWS (Bdim * Nseq)          // 8192
#define OUT_ELEMS (MROWS * Cdim)     // 8,388,608
#define W_ELEMS  (Cdim * Cdim)       // 1,048,576

// Scratch: device globals (no allocations allowed in kernel_launch)
__device__ float g_Q[OUT_ELEMS];
__device__ float g_K[OUT_ELEMS];
__device__ float g_V[OUT_ELEMS];
// fp16 GEMM inputs (E5M10 mantissa == TF32 mantissa; 2x MMA K-depth)
__device__ __half g_X[OUT_ELEMS];
__device__ __half g_O[OUT_ELEMS];    // attn out, rounded to fp16 at store
__device__ __half g_W[4][W_ELEMS];   // Wq, Wk, Wv, Wo

// ---------------------------------------------------------------------------
// Prepass: round fp32 -> fp16 (RN) once.
// blockIdx.y selects tensor: 0=X (8M), 1..4 = weights (1M each).
// ---------------------------------------------------------------------------
__global__ __launch_bounds__(256) void to_half_kernel(
    const float* __restrict__ X,
    const float* __restrict__ Wq, const float* __restrict__ Wk,
    const float* __restrict__ Wv, const float* __restrict__ Wo)
{
    const float* src; __half* dst; int n4;
    switch (blockIdx.y) {
        case 0: src = X;  dst = g_X;    n4 = OUT_ELEMS / 4; break;
        case 1: src = Wq; dst = g_W[0]; n4 = W_ELEMS / 4;   break;
        case 2: src = Wk; dst = g_W[1]; n4 = W_ELEMS / 4;   break;
        case 3: src = Wv; dst = g_W[2]; n4 = W_ELEMS / 4;   break;
        default: src = Wo; dst = g_W[3]; n4 = W_ELEMS / 4;  break;
    }
    const int stride = gridDim.x * blockDim.x;
    for (int i = blockIdx.x * blockDim.x + threadIdx.x; i < n4; i += stride) {
        float4 v = ((const float4*)src)[i];
        ((__half2*)dst)[2 * i]     = __floats2half2_rn(v.x, v.y);
        ((__half2*)dst)[2 * i + 1] = __floats2half2_rn(v.z, v.w);
    }
}

// ---------------------------------------------------------------------------
// fp16 tensor-core GEMM (fp32 accumulate), 3-stage cp.async ring,
// ONE __syncthreads per K-tile (prefetch distance 2 makes the post-compute
// barrier redundant):
//   C[m, n] = sum_k A[m, k] * W[n, k] + bias[n]
// Block tile 128(M) x 256(N), K-tile 64 halfs (16 mainloop iters).
// 256 threads = 8 warps as 2(M) x 4(N); warp tile 64x64 (wmma 16x16x16).
// ---------------------------------------------------------------------------
#define KT       64                      // halfs per K-tile
#define NT       (Cdim / KT)             // 16
#define PITCH    72                      // 64 + 8 pad halfs; rows 144B
#define TILE_A_H (128 * PITCH)           // 9216 halfs
#define TILE_B_H (256 * PITCH)           // 18432 halfs
#define STAGE_H  (TILE_A_H + TILE_B_H)   // 27648 halfs = 55296 B
#define SMEM_BYTES (3 * STAGE_H * 2)     // 3 stages = 165888 B

__device__ __forceinline__ void cp16(void* smem_dst, const void* gmem_src)
{
    unsigned d = (unsigned)__cvta_generic_to_shared(smem_dst);
    asm volatile("cp.async.cg.shared.global [%0], [%1], 16;\n"
                 :: "r"(d), "l"(gmem_src));
}

__device__ __forceinline__ void gemm_block_f16(
    const __half* __restrict__ A, const __half* __restrict__ W,
    const float* __restrict__ bias, float* __restrict__ C)
{
    constexpr int K  = Cdim;
    constexpr int Nf = Cdim;

    extern __shared__ __half smem[];

    const int tid    = threadIdx.x;      // 256 threads
    const int warpId = tid >> 5;
    const int wr     = warpId >> 2;      // 0..1 -> warp row (64 rows each)
    const int wc     = warpId & 3;       // 0..3 -> warp col (64 cols each)
    const int rowBase = blockIdx.y * 128;
    const int colBase = blockIdx.x * 256;

    wmma::fragment<wmma::accumulator, 16, 16, 16, float> acc[4][4];

    // ---- bias init: 16x256 fp32 broadcast tile staged in smem (pitch 256) --
    {
        float* bs = (float*)smem;
        for (int idx = tid; idx < 16 * 256; idx += 256) {
            int r = idx >> 8, c = idx & 255;
            bs[r * 256 + c] = bias[colBase + c];
        }
        __syncthreads();
#pragma unroll
        for (int i = 0; i < 4; i++)
#pragma unroll
            for (int j = 0; j < 4; j++)
                wmma::load_matrix_sync(acc[i][j], &bs[wc * 64 + j * 16], 256,
                                       wmma::mem_row_major);
        __syncthreads();
    }

    // global->smem async copy mapping (16B = 8 halfs per chunk):
    // A tile 128x64 halfs = 1024 chunks (4/thread); B tile 256x64 = 2048 (8/t)
    const int lr = tid >> 3;             // 0..31
    const int lc = (tid & 7) << 3;       // 0,8,...,56 (halfs)

    // prefetch tiles 0 and 1 into stages 0 and 1
#pragma unroll
    for (int p = 0; p < 2; p++) {
        __half* As = smem + p * STAGE_H;
        __half* Bs = As + TILE_A_H;
        const int k0 = p * KT;
#pragma unroll
        for (int i = 0; i < 4; i++) {
            int r = lr + i * 32;
            cp16(&As[r * PITCH + lc], A + (size_t)(rowBase + r) * K + k0 + lc);
        }
#pragma unroll
        for (int i = 0; i < 8; i++) {
            int r = lr + i * 32;
            cp16(&Bs[r * PITCH + lc], W + (size_t)(colBase + r) * K + k0 + lc);
        }
        asm volatile("cp.async.commit_group;\n" ::: "memory");
    }

    int sLoad = 2;   // stage receiving tile kt+2
    int sComp = 0;   // stage holding tile kt
    for (int kt = 0; kt < NT; kt++) {
        // tile kt resident: allow only tile kt+1's group to stay in flight
        if (kt + 1 < NT) {
            asm volatile("cp.async.wait_group 1;\n" ::: "memory");
        } else {
            asm volatile("cp.async.wait_group 0;\n" ::: "memory");
        }
        __syncthreads();   // data visible; all warps done computing tile kt-1

        // prefetch tile kt+2 into sLoad (its last reader finished tile kt-1,
        // ordered before this by the barrier above)
        if (kt + 2 < NT) {
            __half* As = smem + sLoad * STAGE_H;
            __half* Bs = As + TILE_A_H;
            const int k0 = (kt + 2) * KT;
#pragma unroll
            for (int i = 0; i < 4; i++) {
                int r = lr + i * 32;
                cp16(&As[r * PITCH + lc],
                     A + (size_t)(rowBase + r) * K + k0 + lc);
            }
#pragma unroll
            for (int i = 0; i < 8; i++) {
                int r = lr + i * 32;
                cp16(&Bs[r * PITCH + lc],
                     W + (size_t)(colBase + r) * K + k0 + lc);
            }
            asm volatile("cp.async.commit_group;\n" ::: "memory");
        }

        const __half* As = smem + sComp * STAGE_H;
        const __half* Bs = As + TILE_A_H;

#pragma unroll
        for (int kk = 0; kk < KT; kk += 16) {
            wmma::fragment<wmma::matrix_a, 16, 16, 16, __half,
                           wmma::row_major> af[4];
            wmma::fragment<wmma::matrix_b, 16, 16, 16, __half,
                           wmma::col_major> bf[4];
#pragma unroll
            for (int i = 0; i < 4; i++)
                wmma::load_matrix_sync(af[i],
                    &As[(wr * 64 + i * 16) * PITCH + kk], PITCH);
#pragma unroll
            for (int j = 0; j < 4; j++)
                wmma::load_matrix_sync(bf[j],
                    &Bs[(wc * 64 + j * 16) * PITCH + kk], PITCH);
#pragma unroll
            for (int i = 0; i < 4; i++)
#pragma unroll
                for (int j = 0; j < 4; j++)
                    wmma::mma_sync(acc[i][j], af[i], bf[j], acc[i][j]);
        }

        sComp = (sComp == 2) ? 0 : sComp + 1;
        sLoad = (sLoad == 2) ? 0 : sLoad + 1;
    }

    // ---- store ----
#pragma unroll
    for (int i = 0; i < 4; i++)
#pragma unroll
        for (int j = 0; j < 4; j++) {
            int r = rowBase + wr * 64 + i * 16;
            int c = colBase + wc * 64 + j * 16;
            wmma::store_matrix_sync(&C[(size_t)r * Nf + c], acc[i][j], Nf,
                                    wmma::mem_row_major);
        }
}

// QKV: one launch, blockIdx.z selects {Q, K, V}
__global__ __launch_bounds__(256) void qkv_gemm(
    const float* __restrict__ bq, const float* __restrict__ bk,
    const float* __restrict__ bv)
{
    const float* b; float* out;
    if (blockIdx.z == 0)      { b = bq; out = g_Q; }
    else if (blockIdx.z == 1) { b = bk; out = g_K; }
    else                      { b = bv; out = g_V; }
    gemm_block_f16(g_X, g_W[blockIdx.z], b, out);
}

__global__ __launch_bounds__(256) void out_gemm_kernel(
    const float* __restrict__ bo, float* __restrict__ out)
{
    gemm_block_f16(g_O, g_W[3], bo, out);
}

// ---------------------------------------------------------------------------
// Local window attention: one warp per (b, h, n) query.
// Output g_O rounded to fp16 at store (feeds the fp16 out-projection).
// ---------------------------------------------------------------------------
__global__ __launch_bounds__(256) void attn_kernel(float* __restrict__ attn_last)
{
    const int gwarp = (blockIdx.x * blockDim.x + threadIdx.x) >> 5;
    const int lane  = threadIdx.x & 31;
    const int n  = gwarp & (Nseq - 1);
    const int bh = gwarp >> 12;            // Nseq = 2^12
    const int h  = bh & (Hn - 1);
    const int b  = bh >> 4;

    const size_t base = ((size_t)(b * Nseq + n)) * Cdim + h * Dd;
    const float2 qv = *(const float2*)(g_Q + base + lane * 2);

    float s[WW];
#pragma unroll
    for (int w = 0; w < WW; w++) {
        const int pos = n - W2 + w;
        const bool valid = (unsigned)pos < (unsigned)Nseq;
        float partial = 0.f;
        if (valid) {
            const size_t kb = ((size_t)(b * Nseq + pos)) * Cdim + h * Dd;
            const float2 kv = *(const float2*)(g_K + kb + lane * 2);
            partial = qv.x * kv.x + qv.y * kv.y;
        }
        partial += __shfl_xor_sync(0xffffffffu, partial, 16);
        partial += __shfl_xor_sync(0xffffffffu, partial, 8);
        partial += __shfl_xor_sync(0xffffffffu, partial, 4);
        partial += __shfl_xor_sync(0xffffffffu, partial, 2);
        partial += __shfl_xor_sync(0xffffffffu, partial, 1);
        s[w] = valid ? partial * 0.125f : -INFINITY;   // /sqrt(64)
    }

    float m = s[0];
#pragma unroll
    for (int w = 1; w < WW; w++) m = fmaxf(m, s[w]);
    float sum = 0.f;
#pragma unroll
    for (int w = 0; w < WW; w++) {
        const float e = expf(s[w] - m);   // expf(-inf) == 0 for invalid slots
        s[w] = e;
        sum += e;
    }
    const float inv = 1.f / sum;

    float2 acc = make_float2(0.f, 0.f);
#pragma unroll
    for (int w = 0; w < WW; w++) {
        const int pos = n - W2 + w;
        if ((unsigned)pos < (unsigned)Nseq) {
            const size_t vb = ((size_t)(b * Nseq + pos)) * Cdim + h * Dd;
            const float2 vv = *(const float2*)(g_V + vb + lane * 2);
            const float p = s[w] * inv;
            acc.x += p * vv.x;
            acc.y += p * vv.y;
            if (w <= W2 && n == Nseq - 1 && lane == 0)
                attn_last[(b * Hn + h) * (W2 + 1) + w] = p;
        }
    }
    // fp16 store for the out-projection GEMM
    *(__half2*)(g_O + base + lane * 2) = __floats2half2_rn(acc.x, acc.y);
}

// ---------------------------------------------------------------------------
// Launch: fp16 prepass -> QKV (z=3) -> attention -> output projection.
// d_out layout: [out: 8192*1024 floats][attn_last: 2*16*11 floats]
// ---------------------------------------------------------------------------
extern "C" void kernel_launch(void* const* d_in, const int* in_sizes, int n_in,
                              void* d_out, int out_size)
{
    const float* q  = (const float*)d_in[0];
    const float* Wq = (const float*)d_in[1];
    const float* bq = (const float*)d_in[2];
    const float* Wk = (const float*)d_in[3];
    const float* bk = (const float*)d_in[4];
    const float* Wv = (const float*)d_in[5];
    const float* bv = (const float*)d_in[6];
    const float* Wo = (const float*)d_in[7];
    const float* bo = (const float*)d_in[8];
    float* out = (float*)d_out;

    cudaFuncSetAttribute(qkv_gemm,
                         cudaFuncAttributeMaxDynamicSharedMemorySize,
                         SMEM_BYTES);
    cudaFuncSetAttribute(out_gemm_kernel,
                         cudaFuncAttributeMaxDynamicSharedMemorySize,
                         SMEM_BYTES);

    // prepass: round X + 4 weights to fp16 once
    to_half_kernel<<<dim3(256, 5), 256>>>(q, Wq, Wk, Wv, Wo);

    dim3 blk(256);
    dim3 g_qkv(Cdim / 256, MROWS / 128, 3);   // (4, 64, 3)
    qkv_gemm<<<g_qkv, blk, SMEM_BYTES>>>(bq, bk, bv);

    const int total_warps = Bdim * Hn * Nseq;          // 131072
    attn_kernel<<<total_warps / 8, 256>>>(out + OUT_ELEMS);

    dim3 g_o(Cdim / 256, MROWS / 128, 1);
    out_gemm_kernel<<<g_o, blk, SMEM_BYTES>>>(bo, out);
}

// round 12
// speedup vs baseline: 3.5065x; 1.0118x over previous
#include <cuda_runtime.h>
#include <cuda_fp16.h>
#include <cstdint>
#include <mma.h>
#include <math.h>

using namespace nvcuda;

// Problem constants
#define Bdim 2
#define Nseq 4096
#define Cdim 1024
#define Hn   16
#define Dd   64
#define W2   10
#define WW   21

#define MROWS (Bdim * Nseq)          // 8192
#define OUT_ELEMS (MROWS * Cdim)     // 8,388,608
#define W_ELEMS  (Cdim * Cdim)       // 1,048,576

// Scratch: device globals (no allocations allowed in kernel_launch)
// fp16 everywhere between GEMMs: E5M10 mantissa == TF32 mantissa.
__device__ __half g_X[OUT_ELEMS];
__device__ __half g_W[4][W_ELEMS];   // Wq, Wk, Wv, Wo
__device__ __half g_Qh[OUT_ELEMS];
__device__ __half g_Kh[OUT_ELEMS];
__device__ __half g_Vh[OUT_ELEMS];
__device__ __half g_Oh[OUT_ELEMS];   // attn out (fp16), feeds out-projection

// ---------------------------------------------------------------------------
// Prepass: round fp32 -> fp16 (RN) once.
// blockIdx.y selects tensor: 0=X (8M), 1..4 = weights (1M each).
// ---------------------------------------------------------------------------
__global__ __launch_bounds__(256) void to_half_kernel(
    const float* __restrict__ X,
    const float* __restrict__ Wq, const float* __restrict__ Wk,
    const float* __restrict__ Wv, const float* __restrict__ Wo)
{
    const float* src; __half* dst; int n4;
    switch (blockIdx.y) {
        case 0: src = X;  dst = g_X;    n4 = OUT_ELEMS / 4; break;
        case 1: src = Wq; dst = g_W[0]; n4 = W_ELEMS / 4;   break;
        case 2: src = Wk; dst = g_W[1]; n4 = W_ELEMS / 4;   break;
        case 3: src = Wv; dst = g_W[2]; n4 = W_ELEMS / 4;   break;
        default: src = Wo; dst = g_W[3]; n4 = W_ELEMS / 4;  break;
    }
    const int stride = gridDim.x * blockDim.x;
    for (int i = blockIdx.x * blockDim.x + threadIdx.x; i < n4; i += stride) {
        float4 v = ((const float4*)src)[i];
        ((__half2*)dst)[2 * i]     = __floats2half2_rn(v.x, v.y);
        ((__half2*)dst)[2 * i + 1] = __floats2half2_rn(v.z, v.w);
    }
}

// ---------------------------------------------------------------------------
// fp16 tensor-core GEMM (fp32 accumulate), 2-stage cp.async, K-tile 128:
//   C[m, n] = sum_k A[m, k] * W[n, k] + bias[n]
// Block tile 128(M) x 256(N); 8 K-tiles of 128 halfs (8 kk-steps each).
// 256 threads = 8 warps as 2(M) x 4(N); warp tile 64x64 (wmma 16x16x16).
// OutT = __half (staged convert) or float (direct store).
// ---------------------------------------------------------------------------
#define KT       128                     // halfs per K-tile
#define NTt      (Cdim / KT)             // 8
#define PITCH    136                     // 128 + 8 pad halfs; rows 272B
#define TILE_A_H (128 * PITCH)           // 17408 halfs
#define TILE_B_H (256 * PITCH)           // 34816 halfs
#define STAGE_H  (TILE_A_H + TILE_B_H)   // 52224 halfs = 104448 B
#define SMEM_BYTES (2 * STAGE_H * 2)     // 2 stages = 208896 B

__device__ __forceinline__ void cp16(void* smem_dst, const void* gmem_src)
{
    unsigned d = (unsigned)__cvta_generic_to_shared(smem_dst);
    asm volatile("cp.async.cg.shared.global [%0], [%1], 16;\n"
                 :: "r"(d), "l"(gmem_src));
}

template <typename OutT>
__device__ __forceinline__ void gemm_block_f16(
    const __half* __restrict__ A, const __half* __restrict__ W,
    const float* __restrict__ bias, OutT* __restrict__ C)
{
    constexpr int K  = Cdim;
    constexpr int Nf = Cdim;

    extern __shared__ __half smem[];

    const int tid    = threadIdx.x;      // 256 threads
    const int warpId = tid >> 5;
    const int wr     = warpId >> 2;      // 0..1 -> warp row (64 rows each)
    const int wc     = warpId & 3;       // 0..3 -> warp col (64 cols each)
    const int rowBase = blockIdx.y * 128;
    const int colBase = blockIdx.x * 256;

    wmma::fragment<wmma::accumulator, 16, 16, 16, float> acc[4][4];

    // ---- bias init: 16x256 fp32 broadcast tile staged in smem (pitch 256) --
    {
        float* bs = (float*)smem;
        for (int idx = tid; idx < 16 * 256; idx += 256) {
            int r = idx >> 8, c = idx & 255;
            bs[r * 256 + c] = bias[colBase + c];
        }
        __syncthreads();
#pragma unroll
        for (int i = 0; i < 4; i++)
#pragma unroll
            for (int j = 0; j < 4; j++)
                wmma::load_matrix_sync(acc[i][j], &bs[wc * 64 + j * 16], 256,
                                       wmma::mem_row_major);
        __syncthreads();
    }

    // async copy mapping (16B = 8 halfs/chunk; 16 chunks per 128-half row):
    // A tile 128x128 halfs = 2048 chunks (8/thread); B 256x128 = 4096 (16/t)
    // chunk c: row = c >> 4, col = (c & 15) * 8

    // prefetch tile 0 into stage 0
    {
        __half* As = smem;
        __half* Bs = smem + TILE_A_H;
#pragma unroll
        for (int j = 0; j < 8; j++) {
            int c = tid + j * 256, r = c >> 4, col = (c & 15) << 3;
            cp16(&As[r * PITCH + col], A + (size_t)(rowBase + r) * K + col);
        }
#pragma unroll
        for (int j = 0; j < 16; j++) {
            int c = tid + j * 256, r = c >> 4, col = (c & 15) << 3;
            cp16(&Bs[r * PITCH + col], W + (size_t)(colBase + r) * K + col);
        }
        asm volatile("cp.async.commit_group;\n" ::: "memory");
    }

    for (int kt = 0; kt < NTt; kt++) {
        if (kt + 1 < NTt) {
            __half* As = smem + ((kt + 1) & 1) * STAGE_H;
            __half* Bs = As + TILE_A_H;
            const int k0 = (kt + 1) * KT;
#pragma unroll
            for (int j = 0; j < 8; j++) {
                int c = tid + j * 256, r = c >> 4, col = (c & 15) << 3;
                cp16(&As[r * PITCH + col],
                     A + (size_t)(rowBase + r) * K + k0 + col);
            }
#pragma unroll
            for (int j = 0; j < 16; j++) {
                int c = tid + j * 256, r = c >> 4, col = (c & 15) << 3;
                cp16(&Bs[r * PITCH + col],
                     W + (size_t)(colBase + r) * K + k0 + col);
            }
            asm volatile("cp.async.commit_group;\n" ::: "memory");
            asm volatile("cp.async.wait_group 1;\n" ::: "memory");
        } else {
            asm volatile("cp.async.wait_group 0;\n" ::: "memory");
        }
        __syncthreads();   // current stage visible

        const __half* As = smem + (kt & 1) * STAGE_H;
        const __half* Bs = As + TILE_A_H;

#pragma unroll
        for (int kk = 0; kk < KT; kk += 16) {
            wmma::fragment<wmma::matrix_a, 16, 16, 16, __half,
                           wmma::row_major> af[4];
            wmma::fragment<wmma::matrix_b, 16, 16, 16, __half,
                           wmma::col_major> bf[4];
#pragma unroll
            for (int i = 0; i < 4; i++)
                wmma::load_matrix_sync(af[i],
                    &As[(wr * 64 + i * 16) * PITCH + kk], PITCH);
#pragma unroll
            for (int j = 0; j < 4; j++)
                wmma::load_matrix_sync(bf[j],
                    &Bs[(wc * 64 + j * 16) * PITCH + kk], PITCH);
#pragma unroll
            for (int i = 0; i < 4; i++)
#pragma unroll
                for (int j = 0; j < 4; j++)
                    wmma::mma_sync(acc[i][j], af[i], bf[j], acc[i][j]);
        }
        __syncthreads();   // all warps done with this stage before refill
    }

    // ---- store ----
    if constexpr (sizeof(OutT) == 4) {
        // fp32: direct fragment stores
#pragma unroll
        for (int i = 0; i < 4; i++)
#pragma unroll
            for (int j = 0; j < 4; j++) {
                int r = rowBase + wr * 64 + i * 16;
                int c = colBase + wc * 64 + j * 16;
                wmma::store_matrix_sync((float*)C + (size_t)r * Nf + c,
                                        acc[i][j], Nf, wmma::mem_row_major);
            }
    } else {
        // fp16: stage fp32 in smem, convert, coalesced half2 stores
        constexpr int PO = 264;          // 256 + 8 pad floats
        float* st = (float*)smem;        // 128*264*4 = 135168 B < SMEM_BYTES
#pragma unroll
        for (int i = 0; i < 4; i++)
#pragma unroll
            for (int j = 0; j < 4; j++)
                wmma::store_matrix_sync(
                    &st[(size_t)(wr * 64 + i * 16) * PO + wc * 64 + j * 16],
                    acc[i][j], PO, wmma::mem_row_major);
        __syncthreads();
        for (int k = tid; k < 128 * 128; k += 256) {
            int r = k >> 7, c2 = k & 127;
            float x = st[r * PO + 2 * c2];
            float y = st[r * PO + 2 * c2 + 1];
            *(__half2*)((__half*)C + (size_t)(rowBase + r) * Nf + colBase +
                        2 * c2) = __floats2half2_rn(x, y);
        }
    }
}

// QKV: one launch, blockIdx.z selects {Q, K, V}; outputs fp16
__global__ __launch_bounds__(256) void qkv_gemm(
    const float* __restrict__ bq, const float* __restrict__ bk,
    const float* __restrict__ bv)
{
    const float* b; __half* out;
    if (blockIdx.z == 0)      { b = bq; out = g_Qh; }
    else if (blockIdx.z == 1) { b = bk; out = g_Kh; }
    else                      { b = bv; out = g_Vh; }
    gemm_block_f16<__half>(g_X, g_W[blockIdx.z], b, out);
}

__global__ __launch_bounds__(256) void out_gemm_kernel(
    const float* __restrict__ bo, float* __restrict__ out)
{
    gemm_block_f16<float>(g_Oh, g_W[3], bo, out);
}

// ---------------------------------------------------------------------------
// Local window attention: one warp per (b, h, n) query; fp16 Q/K/V loads,
// fp32 math, fp16 output (feeds the fp16 out-projection).
// ---------------------------------------------------------------------------
__global__ __launch_bounds__(256) void attn_kernel(float* __restrict__ attn_last)
{
    const int gwarp = (blockIdx.x * blockDim.x + threadIdx.x) >> 5;
    const int lane  = threadIdx.x & 31;
    const int n  = gwarp & (Nseq - 1);
    const int bh = gwarp >> 12;            // Nseq = 2^12
    const int h  = bh & (Hn - 1);
    const int b  = bh >> 4;

    const size_t base = ((size_t)(b * Nseq + n)) * Cdim + h * Dd;
    const float2 qv = __half22float2(*(const __half2*)(g_Qh + base + lane * 2));

    float s[WW];
#pragma unroll
    for (int w = 0; w < WW; w++) {
        const int pos = n - W2 + w;
        const bool valid = (unsigned)pos < (unsigned)Nseq;
        float partial = 0.f;
        if (valid) {
            const size_t kb = ((size_t)(b * Nseq + pos)) * Cdim + h * Dd;
            const float2 kv =
                __half22float2(*(const __half2*)(g_Kh + kb + lane * 2));
            partial = qv.x * kv.x + qv.y * kv.y;
        }
        partial += __shfl_xor_sync(0xffffffffu, partial, 16);
        partial += __shfl_xor_sync(0xffffffffu, partial, 8);
        partial += __shfl_xor_sync(0xffffffffu, partial, 4);
        partial += __shfl_xor_sync(0xffffffffu, partial, 2);
        partial += __shfl_xor_sync(0xffffffffu, partial, 1);
        s[w] = valid ? partial * 0.125f : -INFINITY;   // /sqrt(64)
    }

    float m = s[0];
#pragma unroll
    for (int w = 1; w < WW; w++) m = fmaxf(m, s[w]);
    float sum = 0.f;
#pragma unroll
    for (int w = 0; w < WW; w++) {
        const float e = expf(s[w] - m);   // expf(-inf) == 0 for invalid slots
        s[w] = e;
        sum += e;
    }
    const float inv = 1.f / sum;

    float2 acc = make_float2(0.f, 0.f);
#pragma unroll
    for (int w = 0; w < WW; w++) {
        const int pos = n - W2 + w;
        if ((unsigned)pos < (unsigned)Nseq) {
            const size_t vb = ((size_t)(b * Nseq + pos)) * Cdim + h * Dd;
            const float2 vv =
                __half22float2(*(const __half2*)(g_Vh + vb + lane * 2));
            const float p = s[w] * inv;
            acc.x += p * vv.x;
            acc.y += p * vv.y;
            if (w <= W2 && n == Nseq - 1 && lane == 0)
                attn_last[(b * Hn + h) * (W2 + 1) + w] = p;
        }
    }
    *(__half2*)(g_Oh + base + lane * 2) = __floats2half2_rn(acc.x, acc.y);
}

// ---------------------------------------------------------------------------
// Launch: fp16 prepass -> QKV (z=3) -> attention -> output projection.
// d_out layout: [out: 8192*1024 floats][attn_last: 2*16*11 floats]
// ---------------------------------------------------------------------------
extern "C" void kernel_launch(void* const* d_in, const int* in_sizes, int n_in,
                              void* d_out, int out_size)
{
    const float* q  = (const float*)d_in[0];
    const float* Wq = (const float*)d_in[1];
    const float* bq = (const float*)d_in[2];
    const float* Wk = (const float*)d_in[3];
    const float* bk = (const float*)d_in[4];
    const float* Wv = (const float*)d_in[5];
    const float* bv = (const float*)d_in[6];
    const float* Wo = (const float*)d_in[7];
    const float* bo = (const float*)d_in[8];
    float* out = (float*)d_out;

    cudaFuncSetAttribute(qkv_gemm,
                         cudaFuncAttributeMaxDynamicSharedMemorySize,
                         SMEM_BYTES);
    cudaFuncSetAttribute(out_gemm_kernel,
                         cudaFuncAttributeMaxDynamicSharedMemorySize,
                         SMEM_BYTES);

    // prepass: round X + 4 weights to fp16 once
    to_half_kernel<<<dim3(256, 5), 256>>>(q, Wq, Wk, Wv, Wo);

    dim3 blk(256);
    dim3 g_qkv(Cdim / 256, MROWS / 128, 3);   // (4, 64, 3)
    qkv_gemm<<<g_qkv, blk, SMEM_BYTES>>>(bq, bk, bv);

    const int total_warps = Bdim * Hn * Nseq;          // 131072
    attn_kernel<<<total_warps / 8, 256>>>(out + OUT_ELEMS);

    dim3 g_o(Cdim / 256, MROWS / 128, 1);
    out_gemm_kernel<<<g_o, blk, SMEM_BYTES>>>(bo, out);
}

// round 13
// speedup vs baseline: 4.1337x; 1.1789x over previous
#include <cuda_runtime.h>
#include <cuda_fp16.h>
#include <cstdint>
#include <mma.h>
#include <math.h>

using namespace nvcuda;

// Problem constants
#define Bdim 2
#define Nseq 4096
#define Cdim 1024
#define Hn   16
#define Dd   64
#define W2   10
#define WW   21

#define MROWS (Bdim * Nseq)          // 8192
#define OUT_ELEMS (MROWS * Cdim)     // 8,388,608
#define W_ELEMS  (Cdim * Cdim)       // 1,048,576

// Scratch: device globals (no allocations allowed in kernel_launch)
// fp16 everywhere between GEMMs: E5M10 mantissa == TF32 mantissa.
__device__ __half g_X[OUT_ELEMS];
__device__ __half g_W[4][W_ELEMS];   // Wq, Wk, Wv, Wo
__device__ __half g_Qh[OUT_ELEMS];
__device__ __half g_Kh[OUT_ELEMS];
__device__ __half g_Vh[OUT_ELEMS];
__device__ __half g_Oh[OUT_ELEMS];   // attn out (fp16), feeds out-projection

// ---------------------------------------------------------------------------
// Prepass: round fp32 -> fp16 (RN) once.
// blockIdx.y selects tensor: 0=X (8M), 1..4 = weights (1M each).
// ---------------------------------------------------------------------------
__global__ __launch_bounds__(256) void to_half_kernel(
    const float* __restrict__ X,
    const float* __restrict__ Wq, const float* __restrict__ Wk,
    const float* __restrict__ Wv, const float* __restrict__ Wo)
{
    const float* src; __half* dst; int n4;
    switch (blockIdx.y) {
        case 0: src = X;  dst = g_X;    n4 = OUT_ELEMS / 4; break;
        case 1: src = Wq; dst = g_W[0]; n4 = W_ELEMS / 4;   break;
        case 2: src = Wk; dst = g_W[1]; n4 = W_ELEMS / 4;   break;
        case 3: src = Wv; dst = g_W[2]; n4 = W_ELEMS / 4;   break;
        default: src = Wo; dst = g_W[3]; n4 = W_ELEMS / 4;  break;
    }
    const int stride = gridDim.x * blockDim.x;
    for (int i = blockIdx.x * blockDim.x + threadIdx.x; i < n4; i += stride) {
        float4 v = ((const float4*)src)[i];
        ((__half2*)dst)[2 * i]     = __floats2half2_rn(v.x, v.y);
        ((__half2*)dst)[2 * i + 1] = __floats2half2_rn(v.z, v.w);
    }
}

// ---------------------------------------------------------------------------
// fp16 tensor-core GEMM (fp32 accumulate), 2-stage cp.async, K-tile 128:
//   C[m, n] = sum_k A[m, k] * W[n, k] + bias[n]
// Block tile 128(M) x 256(N); 8 K-tiles of 128 halfs (8 kk-steps each).
// 256 threads = 8 warps as 2(M) x 4(N); warp tile 64x64 (wmma 16x16x16).
// OutT = __half (staged convert) or float (direct store).
// ---------------------------------------------------------------------------
#define KT       128                     // halfs per K-tile
#define NTt      (Cdim / KT)             // 8
#define PITCH    136                     // 128 + 8 pad halfs; rows 272B
#define TILE_A_H (128 * PITCH)           // 17408 halfs
#define TILE_B_H (256 * PITCH)           // 34816 halfs
#define STAGE_H  (TILE_A_H + TILE_B_H)   // 52224 halfs = 104448 B
#define SMEM_BYTES (2 * STAGE_H * 2)     // 2 stages = 208896 B

__device__ __forceinline__ void cp16(void* smem_dst, const void* gmem_src)
{
    unsigned d = (unsigned)__cvta_generic_to_shared(smem_dst);
    asm volatile("cp.async.cg.shared.global [%0], [%1], 16;\n"
                 :: "r"(d), "l"(gmem_src));
}

template <typename OutT>
__device__ __forceinline__ void gemm_block_f16(
    const __half* __restrict__ A, const __half* __restrict__ W,
    const float* __restrict__ bias, OutT* __restrict__ C)
{
    constexpr int K  = Cdim;
    constexpr int Nf = Cdim;

    extern __shared__ __half smem[];

    const int tid    = threadIdx.x;      // 256 threads
    const int warpId = tid >> 5;
    const int wr     = warpId >> 2;      // 0..1 -> warp row (64 rows each)
    const int wc     = warpId & 3;       // 0..3 -> warp col (64 cols each)
    const int rowBase = blockIdx.y * 128;
    const int colBase = blockIdx.x * 256;

    wmma::fragment<wmma::accumulator, 16, 16, 16, float> acc[4][4];

    // ---- bias init: 16x256 fp32 broadcast tile staged in smem (pitch 256) --
    {
        float* bs = (float*)smem;
        for (int idx = tid; idx < 16 * 256; idx += 256) {
            int r = idx >> 8, c = idx & 255;
            bs[r * 256 + c] = bias[colBase + c];
        }
        __syncthreads();
#pragma unroll
        for (int i = 0; i < 4; i++)
#pragma unroll
            for (int j = 0; j < 4; j++)
                wmma::load_matrix_sync(acc[i][j], &bs[wc * 64 + j * 16], 256,
                                       wmma::mem_row_major);
        __syncthreads();
    }

    // async copy mapping (16B = 8 halfs/chunk; 16 chunks per 128-half row):
    // A tile 128x128 halfs = 2048 chunks (8/thread); B 256x128 = 4096 (16/t)

    // prefetch tile 0 into stage 0
    {
        __half* As = smem;
        __half* Bs = smem + TILE_A_H;
#pragma unroll
        for (int j = 0; j < 8; j++) {
            int c = tid + j * 256, r = c >> 4, col = (c & 15) << 3;
            cp16(&As[r * PITCH + col], A + (size_t)(rowBase + r) * K + col);
        }
#pragma unroll
        for (int j = 0; j < 16; j++) {
            int c = tid + j * 256, r = c >> 4, col = (c & 15) << 3;
            cp16(&Bs[r * PITCH + col], W + (size_t)(colBase + r) * K + col);
        }
        asm volatile("cp.async.commit_group;\n" ::: "memory");
    }

    for (int kt = 0; kt < NTt; kt++) {
        if (kt + 1 < NTt) {
            __half* As = smem + ((kt + 1) & 1) * STAGE_H;
            __half* Bs = As + TILE_A_H;
            const int k0 = (kt + 1) * KT;
#pragma unroll
            for (int j = 0; j < 8; j++) {
                int c = tid + j * 256, r = c >> 4, col = (c & 15) << 3;
                cp16(&As[r * PITCH + col],
                     A + (size_t)(rowBase + r) * K + k0 + col);
            }
#pragma unroll
            for (int j = 0; j < 16; j++) {
                int c = tid + j * 256, r = c >> 4, col = (c & 15) << 3;
                cp16(&Bs[r * PITCH + col],
                     W + (size_t)(colBase + r) * K + k0 + col);
            }
            asm volatile("cp.async.commit_group;\n" ::: "memory");
            asm volatile("cp.async.wait_group 1;\n" ::: "memory");
        } else {
            asm volatile("cp.async.wait_group 0;\n" ::: "memory");
        }
        __syncthreads();   // current stage visible

        const __half* As = smem + (kt & 1) * STAGE_H;
        const __half* Bs = As + TILE_A_H;

#pragma unroll
        for (int kk = 0; kk < KT; kk += 16) {
            wmma::fragment<wmma::matrix_a, 16, 16, 16, __half,
                           wmma::row_major> af[4];
            wmma::fragment<wmma::matrix_b, 16, 16, 16, __half,
                           wmma::col_major> bf[4];
#pragma unroll
            for (int i = 0; i < 4; i++)
                wmma::load_matrix_sync(af[i],
                    &As[(wr * 64 + i * 16) * PITCH + kk], PITCH);
#pragma unroll
            for (int j = 0; j < 4; j++)
                wmma::load_matrix_sync(bf[j],
                    &Bs[(wc * 64 + j * 16) * PITCH + kk], PITCH);
#pragma unroll
            for (int i = 0; i < 4; i++)
#pragma unroll
                for (int j = 0; j < 4; j++)
                    wmma::mma_sync(acc[i][j], af[i], bf[j], acc[i][j]);
        }
        __syncthreads();   // all warps done with this stage before refill
    }

    // ---- store ----
    if constexpr (sizeof(OutT) == 4) {
#pragma unroll
        for (int i = 0; i < 4; i++)
#pragma unroll
            for (int j = 0; j < 4; j++) {
                int r = rowBase + wr * 64 + i * 16;
                int c = colBase + wc * 64 + j * 16;
                wmma::store_matrix_sync((float*)C + (size_t)r * Nf + c,
                                        acc[i][j], Nf, wmma::mem_row_major);
            }
    } else {
        // fp16: stage fp32 in smem, convert, coalesced half2 stores
        constexpr int PO = 264;          // 256 + 8 pad floats
        float* st = (float*)smem;        // 128*264*4 = 135168 B < SMEM_BYTES
#pragma unroll
        for (int i = 0; i < 4; i++)
#pragma unroll
            for (int j = 0; j < 4; j++)
                wmma::store_matrix_sync(
                    &st[(size_t)(wr * 64 + i * 16) * PO + wc * 64 + j * 16],
                    acc[i][j], PO, wmma::mem_row_major);
        __syncthreads();
        for (int k = tid; k < 128 * 128; k += 256) {
            int r = k >> 7, c2 = k & 127;
            float x = st[r * PO + 2 * c2];
            float y = st[r * PO + 2 * c2 + 1];
            *(__half2*)((__half*)C + (size_t)(rowBase + r) * Nf + colBase +
                        2 * c2) = __floats2half2_rn(x, y);
        }
    }
}

// QKV: one launch, blockIdx.z selects {Q, K, V}; outputs fp16
__global__ __launch_bounds__(256) void qkv_gemm(
    const float* __restrict__ bq, const float* __restrict__ bk,
    const float* __restrict__ bv)
{
    const float* b; __half* out;
    if (blockIdx.z == 0)      { b = bq; out = g_Qh; }
    else if (blockIdx.z == 1) { b = bk; out = g_Kh; }
    else                      { b = bv; out = g_Vh; }
    gemm_block_f16<__half>(g_X, g_W[blockIdx.z], b, out);
}

__global__ __launch_bounds__(256) void out_gemm_kernel(
    const float* __restrict__ bo, float* __restrict__ out)
{
    gemm_block_f16<float>(g_Oh, g_W[3], bo, out);
}

// ---------------------------------------------------------------------------
// Local window attention, thread-per-query with smem-staged K/V.
// Block = 256 consecutive queries of one (b, h). Window rows [n0-10, n0+265]
// staged in smem, rows padded to 148B (37 banks, coprime 32 -> conflict-free
// when lane l reads row l + w). No shuffles, no reductions.
// ---------------------------------------------------------------------------
#define AT_ROWS  276                     // 256 + 2*W2
#define AT_PITCH 74                      // 64 + 10 pad halfs -> 148B rows
#define AT_SMEM  (2 * AT_ROWS * AT_PITCH * 2)   // 81696 B

__global__ __launch_bounds__(256) void attn_kernel(float* __restrict__ attn_last)
{
    extern __shared__ __half asm_[];
    __half* sK = asm_;
    __half* sV = asm_ + AT_ROWS * AT_PITCH;

    const int t  = threadIdx.x;
    const int n0 = blockIdx.x << 8;        // 256 queries per block
    const int h  = blockIdx.y;
    const int b  = blockIdx.z;
    const int n  = n0 + t;
    const size_t rowbase = (size_t)b * Nseq * Cdim + h * Dd;

    // ---- stage Q coalesced into sV, then into registers ----
    for (int i = t; i < 256 * 32; i += 256) {
        int r = i >> 5, c = i & 31;
        *(uint32_t*)(sV + r * AT_PITCH + 2 * c) =
            *(const uint32_t*)(g_Qh + rowbase + (size_t)(n0 + r) * Cdim + 2 * c);
    }
    __syncthreads();
    float q[64];
#pragma unroll
    for (int j = 0; j < 32; j++) {
        float2 f = __half22float2(((const __half2*)(sV + t * AT_PITCH))[j]);
        q[2 * j] = f.x; q[2 * j + 1] = f.y;
    }
    __syncthreads();

    // ---- stage K and V window (zero-filled outside [0, N)) ----
    for (int i = t; i < AT_ROWS * 32; i += 256) {
        int r = i >> 5, c = i & 31;
        int gr = n0 - W2 + r;
        uint32_t kw = 0, vw = 0;
        if ((unsigned)gr < (unsigned)Nseq) {
            size_t off = rowbase + (size_t)gr * Cdim + 2 * c;
            kw = *(const uint32_t*)(g_Kh + off);
            vw = *(const uint32_t*)(g_Vh + off);
        }
        *(uint32_t*)(sK + r * AT_PITCH + 2 * c) = kw;
        *(uint32_t*)(sV + r * AT_PITCH + 2 * c) = vw;
    }
    __syncthreads();

    // ---- scores: query t vs smem rows t..t+20 (global n-10..n+10) ----
    float s[WW];
#pragma unroll
    for (int w = 0; w < WW; w++) {
        const int pos = n - W2 + w;
        const __half2* kr = (const __half2*)(sK + (t + w) * AT_PITCH);
        float d = 0.f;
#pragma unroll
        for (int j = 0; j < 32; j++) {
            float2 kf = __half22float2(kr[j]);
            d += q[2 * j] * kf.x + q[2 * j + 1] * kf.y;
        }
        s[w] = ((unsigned)pos < (unsigned)Nseq) ? d * 0.125f : -INFINITY;
    }

    float m = s[0];
#pragma unroll
    for (int w = 1; w < WW; w++) m = fmaxf(m, s[w]);
    float sum = 0.f;
#pragma unroll
    for (int w = 0; w < WW; w++) {
        const float e = __expf(s[w] - m);   // exp(-inf) == 0 for invalid
        s[w] = e;
        sum += e;
    }
    const float inv = 1.f / sum;

    // ---- weighted V sum ----
    float o[64];
#pragma unroll
    for (int j = 0; j < 64; j++) o[j] = 0.f;
#pragma unroll
    for (int w = 0; w < WW; w++) {
        const float p = s[w] * inv;
        const __half2* vr = (const __half2*)(sV + (t + w) * AT_PITCH);
#pragma unroll
        for (int j = 0; j < 32; j++) {
            float2 vf = __half22float2(vr[j]);
            o[2 * j]     += p * vf.x;
            o[2 * j + 1] += p * vf.y;
        }
    }

    if (n == Nseq - 1) {
#pragma unroll
        for (int w = 0; w <= W2; w++)
            attn_last[(b * Hn + h) * (W2 + 1) + w] = s[w] * inv;
    }

    // ---- write O: regs -> smem (reuse sK) -> coalesced gmem ----
    __syncthreads();   // all reads of sK done
#pragma unroll
    for (int j = 0; j < 32; j++)
        ((__half2*)(sK + t * AT_PITCH))[j] =
            __floats2half2_rn(o[2 * j], o[2 * j + 1]);
    __syncthreads();
    for (int i = t; i < 256 * 32; i += 256) {
        int r = i >> 5, c = i & 31;
        *(uint32_t*)(g_Oh + rowbase + (size_t)(n0 + r) * Cdim + 2 * c) =
            *(const uint32_t*)(sK + r * AT_PITCH + 2 * c);
    }
}

// ---------------------------------------------------------------------------
// Launch: fp16 prepass -> QKV (z=3) -> attention -> output projection.
// d_out layout: [out: 8192*1024 floats][attn_last: 2*16*11 floats]
// ---------------------------------------------------------------------------
extern "C" void kernel_launch(void* const* d_in, const int* in_sizes, int n_in,
                              void* d_out, int out_size)
{
    const float* q  = (const float*)d_in[0];
    const float* Wq = (const float*)d_in[1];
    const float* bq = (const float*)d_in[2];
    const float* Wk = (const float*)d_in[3];
    const float* bk = (const float*)d_in[4];
    const float* Wv = (const float*)d_in[5];
    const float* bv = (const float*)d_in[6];
    const float* Wo = (const float*)d_in[7];
    const float* bo = (const float*)d_in[8];
    float* out = (float*)d_out;

    cudaFuncSetAttribute(qkv_gemm,
                         cudaFuncAttributeMaxDynamicSharedMemorySize,
                         SMEM_BYTES);
    cudaFuncSetAttribute(out_gemm_kernel,
                         cudaFuncAttributeMaxDynamicSharedMemorySize,
                         SMEM_BYTES);
    cudaFuncSetAttribute(attn_kernel,
                         cudaFuncAttributeMaxDynamicSharedMemorySize,
                         AT_SMEM);

    // prepass: round X + 4 weights to fp16 once
    to_half_kernel<<<dim3(256, 5), 256>>>(q, Wq, Wk, Wv, Wo);

    dim3 blk(256);
    dim3 g_qkv(Cdim / 256, MROWS / 128, 3);   // (4, 64, 3)
    qkv_gemm<<<g_qkv, blk, SMEM_BYTES>>>(bq, bk, bv);

    attn_kernel<<<dim3(Nseq / 256, Hn, Bdim), 256, AT_SMEM>>>(out + OUT_ELEMS);

    dim3 g_o(Cdim / 256, MROWS / 128, 1);
    out_gemm_kernel<<<g_o, blk, SMEM_BYTES>>>(bo, out);
}

// round 15
// speedup vs baseline: 4.4690x; 1.0811x over previous
#include <cuda_runtime.h>
#include <cuda_fp16.h>
#include <cstdint>
#include <mma.h>
#include <math.h>

using namespace nvcuda;

// Problem constants
#define Bdim 2
#define Nseq 4096
#define Cdim 1024
#define Hn   16
#define Dd   64
#define W2   10
#define WW   21

#define MROWS (Bdim * Nseq)          // 8192
#define OUT_ELEMS (MROWS * Cdim)     // 8,388,608
#define W_ELEMS  (Cdim * Cdim)       // 1,048,576

// Scratch: device globals (no allocations allowed in kernel_launch)
// fp16 everywhere between GEMMs: E5M10 mantissa == TF32 mantissa.
__device__ __half g_X[OUT_ELEMS];
__device__ __half g_W[4][W_ELEMS];   // Wq, Wk, Wv, Wo
__device__ __half g_Qh[OUT_ELEMS];
__device__ __half g_Kh[OUT_ELEMS];
__device__ __half g_Vh[OUT_ELEMS];
__device__ __half g_Oh[OUT_ELEMS];   // attn out (fp16), feeds out-projection

// ---------------------------------------------------------------------------
// Prepass: round fp32 -> fp16 (RN) once.
// blockIdx.y selects tensor: 0=X (8M), 1..4 = weights (1M each).
// ---------------------------------------------------------------------------
__global__ __launch_bounds__(256) void to_half_kernel(
    const float* __restrict__ X,
    const float* __restrict__ Wq, const float* __restrict__ Wk,
    const float* __restrict__ Wv, const float* __restrict__ Wo)
{
    const float* src; __half* dst; int n4;
    switch (blockIdx.y) {
        case 0: src = X;  dst = g_X;    n4 = OUT_ELEMS / 4; break;
        case 1: src = Wq; dst = g_W[0]; n4 = W_ELEMS / 4;   break;
        case 2: src = Wk; dst = g_W[1]; n4 = W_ELEMS / 4;   break;
        case 3: src = Wv; dst = g_W[2]; n4 = W_ELEMS / 4;   break;
        default: src = Wo; dst = g_W[3]; n4 = W_ELEMS / 4;  break;
    }
    const int stride = gridDim.x * blockDim.x;
    for (int i = blockIdx.x * blockDim.x + threadIdx.x; i < n4; i += stride) {
        float4 v = ((const float4*)src)[i];
        ((__half2*)dst)[2 * i]     = __floats2half2_rn(v.x, v.y);
        ((__half2*)dst)[2 * i + 1] = __floats2half2_rn(v.z, v.w);
    }
}

// ---------------------------------------------------------------------------
// fp16 tensor-core GEMM (fp32 accumulate), 2-stage cp.async, K-tile 128:
//   C[m, n] = sum_k A[m, k] * W[n, k] + bias[n]
// Block tile 128(M) x 256(N); 8 K-tiles of 128 halfs (8 kk-steps each).
// 256 threads = 8 warps as 2(M) x 4(N); warp tile 64x64 (wmma 16x16x16).
// OutT = __half (direct fragment-converted store) or float (direct store).
// ---------------------------------------------------------------------------
#define KT       128                     // halfs per K-tile
#define NTt      (Cdim / KT)             // 8
#define PITCH    136                     // 128 + 8 pad halfs; rows 272B
#define TILE_A_H (128 * PITCH)           // 17408 halfs
#define TILE_B_H (256 * PITCH)           // 34816 halfs
#define STAGE_H  (TILE_A_H + TILE_B_H)   // 52224 halfs = 104448 B
#define SMEM_BYTES (2 * STAGE_H * 2)     // 2 stages = 208896 B

__device__ __forceinline__ void cp16(void* smem_dst, const void* gmem_src)
{
    unsigned d = (unsigned)__cvta_generic_to_shared(smem_dst);
    asm volatile("cp.async.cg.shared.global [%0], [%1], 16;\n"
                 :: "r"(d), "l"(gmem_src));
}

template <typename OutT>
__device__ __forceinline__ void gemm_block_f16(
    const __half* __restrict__ A, const __half* __restrict__ W,
    const float* __restrict__ bias, OutT* __restrict__ C)
{
    constexpr int K  = Cdim;
    constexpr int Nf = Cdim;

    extern __shared__ __half smem[];

    const int tid    = threadIdx.x;      // 256 threads
    const int warpId = tid >> 5;
    const int wr     = warpId >> 2;      // 0..1 -> warp row (64 rows each)
    const int wc     = warpId & 3;       // 0..3 -> warp col (64 cols each)
    const int rowBase = blockIdx.y * 128;
    const int colBase = blockIdx.x * 256;

    wmma::fragment<wmma::accumulator, 16, 16, 16, float> acc[4][4];

    // ---- bias init: 16x256 fp32 broadcast tile staged in smem (pitch 256) --
    {
        float* bs = (float*)smem;
        for (int idx = tid; idx < 16 * 256; idx += 256) {
            int r = idx >> 8, c = idx & 255;
            bs[r * 256 + c] = bias[colBase + c];
        }
        __syncthreads();
#pragma unroll
        for (int i = 0; i < 4; i++)
#pragma unroll
            for (int j = 0; j < 4; j++)
                wmma::load_matrix_sync(acc[i][j], &bs[wc * 64 + j * 16], 256,
                                       wmma::mem_row_major);
        __syncthreads();
    }

    // async copy mapping (16B = 8 halfs/chunk; 16 chunks per 128-half row):
    // A tile 128x128 halfs = 2048 chunks (8/thread); B 256x128 = 4096 (16/t)

    // prefetch tile 0 into stage 0
    {
        __half* As = smem;
        __half* Bs = smem + TILE_A_H;
#pragma unroll
        for (int j = 0; j < 8; j++) {
            int c = tid + j * 256, r = c >> 4, col = (c & 15) << 3;
            cp16(&As[r * PITCH + col], A + (size_t)(rowBase + r) * K + col);
        }
#pragma unroll
        for (int j = 0; j < 16; j++) {
            int c = tid + j * 256, r = c >> 4, col = (c & 15) << 3;
            cp16(&Bs[r * PITCH + col], W + (size_t)(colBase + r) * K + col);
        }
        asm volatile("cp.async.commit_group;\n" ::: "memory");
    }

    for (int kt = 0; kt < NTt; kt++) {
        if (kt + 1 < NTt) {
            __half* As = smem + ((kt + 1) & 1) * STAGE_H;
            __half* Bs = As + TILE_A_H;
            const int k0 = (kt + 1) * KT;
#pragma unroll
            for (int j = 0; j < 8; j++) {
                int c = tid + j * 256, r = c >> 4, col = (c & 15) << 3;
                cp16(&As[r * PITCH + col],
                     A + (size_t)(rowBase + r) * K + k0 + col);
            }
#pragma unroll
            for (int j = 0; j < 16; j++) {
                int c = tid + j * 256, r = c >> 4, col = (c & 15) << 3;
                cp16(&Bs[r * PITCH + col],
                     W + (size_t)(colBase + r) * K + k0 + col);
            }
            asm volatile("cp.async.commit_group;\n" ::: "memory");
            asm volatile("cp.async.wait_group 1;\n" ::: "memory");
        } else {
            asm volatile("cp.async.wait_group 0;\n" ::: "memory");
        }
        __syncthreads();   // current stage visible

        const __half* As = smem + (kt & 1) * STAGE_H;
        const __half* Bs = As + TILE_A_H;

#pragma unroll
        for (int kk = 0; kk < KT; kk += 16) {
            wmma::fragment<wmma::matrix_a, 16, 16, 16, __half,
                           wmma::row_major> af[4];
            wmma::fragment<wmma::matrix_b, 16, 16, 16, __half,
                           wmma::col_major> bf[4];
#pragma unroll
            for (int i = 0; i < 4; i++)
                wmma::load_matrix_sync(af[i],
                    &As[(wr * 64 + i * 16) * PITCH + kk], PITCH);
#pragma unroll
            for (int j = 0; j < 4; j++)
                wmma::load_matrix_sync(bf[j],
                    &Bs[(wc * 64 + j * 16) * PITCH + kk], PITCH);
#pragma unroll
            for (int i = 0; i < 4; i++)
#pragma unroll
                for (int j = 0; j < 4; j++)
                    wmma::mma_sync(acc[i][j], af[i], bf[j], acc[i][j]);
        }
        __syncthreads();   // all warps done with this stage before refill
    }

    // ---- store ----
    if constexpr (sizeof(OutT) == 4) {
#pragma unroll
        for (int i = 0; i < 4; i++)
#pragma unroll
            for (int j = 0; j < 4; j++) {
                int r = rowBase + wr * 64 + i * 16;
                int c = colBase + wc * 64 + j * 16;
                wmma::store_matrix_sync((float*)C + (size_t)r * Nf + c,
                                        acc[i][j], Nf, wmma::mem_row_major);
            }
    } else {
        // fp16: elementwise-convert each fp32 accumulator fragment into a
        // half accumulator fragment (same logical element order) and store
        // directly to gmem -- no smem staging, no barriers.
#pragma unroll
        for (int i = 0; i < 4; i++)
#pragma unroll
            for (int j = 0; j < 4; j++) {
                wmma::fragment<wmma::accumulator, 16, 16, 16, __half> hacc;
#pragma unroll
                for (int t = 0; t < hacc.num_elements; t++)
                    hacc.x[t] = __float2half(acc[i][j].x[t]);
                int r = rowBase + wr * 64 + i * 16;
                int c = colBase + wc * 64 + j * 16;
                wmma::store_matrix_sync((__half*)C + (size_t)r * Nf + c,
                                        hacc, Nf, wmma::mem_row_major);
            }
    }
}

// QKV: one launch, blockIdx.z selects {Q, K, V}; outputs fp16
__global__ __launch_bounds__(256) void qkv_gemm(
    const float* __restrict__ bq, const float* __restrict__ bk,
    const float* __restrict__ bv)
{
    const float* b; __half* out;
    if (blockIdx.z == 0)      { b = bq; out = g_Qh; }
    else if (blockIdx.z == 1) { b = bk; out = g_Kh; }
    else                      { b = bv; out = g_Vh; }
    gemm_block_f16<__half>(g_X, g_W[blockIdx.z], b, out);
}

__global__ __launch_bounds__(256) void out_gemm_kernel(
    const float* __restrict__ bo, float* __restrict__ out)
{
    gemm_block_f16<float>(g_Oh, g_W[3], bo, out);
}

// ---------------------------------------------------------------------------
// Local window attention, thread-per-query with smem-staged K/V.
// Block = 256 consecutive queries of one (b, h). Window rows [n0-10, n0+265]
// staged in smem at pitch 72 halfs (144B: 16B-aligned rows, stride 36 banks
// -> conflict-free LDS.128 for all phases). All smem traffic is 128-bit.
// ---------------------------------------------------------------------------
#define AT_ROWS  276                     // 256 + 2*W2
#define AT_PITCH 72                      // halfs; 144B rows, 16B aligned
#define AT_SMEM  (2 * AT_ROWS * AT_PITCH * 2)   // 79488 B

__global__ __launch_bounds__(256) void attn_kernel(float* __restrict__ attn_last)
{
    extern __shared__ __half asm_[];
    __half* sK = asm_;
    __half* sV = asm_ + AT_ROWS * AT_PITCH;

    const int t  = threadIdx.x;
    const int n0 = blockIdx.x << 8;        // 256 queries per block
    const int h  = blockIdx.y;
    const int b  = blockIdx.z;
    const int n  = n0 + t;
    const size_t rowbase = (size_t)b * Nseq * Cdim + h * Dd;

    // ---- stage Q coalesced into sV (uint4 = 8 halfs), then to registers ----
    for (int i = t; i < 256 * 8; i += 256) {
        int r = i >> 3, c = i & 7;
        *(uint4*)(sV + r * AT_PITCH + c * 8) =
            *(const uint4*)(g_Qh + rowbase + (size_t)(n0 + r) * Cdim + c * 8);
    }
    __syncthreads();
    float q[64];
#pragma unroll
    for (int j = 0; j < 8; j++) {
        uint4 raw = ((const uint4*)(sV + t * AT_PITCH))[j];
        const __half2* hp = (const __half2*)&raw;
#pragma unroll
        for (int e = 0; e < 4; e++) {
            float2 f = __half22float2(hp[e]);
            q[j * 8 + 2 * e]     = f.x;
            q[j * 8 + 2 * e + 1] = f.y;
        }
    }
    __syncthreads();

    // ---- stage K and V window (zero-filled outside [0, N)), uint4 grain ----
    for (int i = t; i < AT_ROWS * 8; i += 256) {
        int r = i >> 3, c = i & 7;
        int gr = n0 - W2 + r;
        uint4 kw = make_uint4(0, 0, 0, 0), vw = make_uint4(0, 0, 0, 0);
        if ((unsigned)gr < (unsigned)Nseq) {
            size_t off = rowbase + (size_t)gr * Cdim + c * 8;
            kw = *(const uint4*)(g_Kh + off);
            vw = *(const uint4*)(g_Vh + off);
        }
        *(uint4*)(sK + r * AT_PITCH + c * 8) = kw;
        *(uint4*)(sV + r * AT_PITCH + c * 8) = vw;
    }
    __syncthreads();

    // ---- scores: query t vs smem rows t..t+20 (global n-10..n+10) ----
    float s[WW];
#pragma unroll
    for (int w = 0; w < WW; w++) {
        const int pos = n - W2 + w;
        const uint4* kr = (const uint4*)(sK + (t + w) * AT_PITCH);
        float d = 0.f;
#pragma unroll
        for (int j = 0; j < 8; j++) {
            uint4 raw = kr[j];
            const __half2* hp = (const __half2*)&raw;
#pragma unroll
            for (int e = 0; e < 4; e++) {
                float2 kf = __half22float2(hp[e]);
                d += q[j * 8 + 2 * e] * kf.x + q[j * 8 + 2 * e + 1] * kf.y;
            }
        }
        s[w] = ((unsigned)pos < (unsigned)Nseq) ? d * 0.125f : -INFINITY;
    }

    float m = s[0];
#pragma unroll
    for (int w = 1; w < WW; w++) m = fmaxf(m, s[w]);
    float sum = 0.f;
#pragma unroll
    for (int w = 0; w < WW; w++) {
        const float e = __expf(s[w] - m);   // exp(-inf) == 0 for invalid
        s[w] = e;
        sum += e;
    }
    const float inv = 1.f / sum;

    // ---- weighted V sum ----
    float o[64];
#pragma unroll
    for (int j = 0; j < 64; j++) o[j] = 0.f;
#pragma unroll
    for (int w = 0; w < WW; w++) {
        const float p = s[w] * inv;
        const uint4* vr = (const uint4*)(sV + (t + w) * AT_PITCH);
#pragma unroll
        for (int j = 0; j < 8; j++) {
            uint4 raw = vr[j];
            const __half2* hp = (const __half2*)&raw;
#pragma unroll
            for (int e = 0; e < 4; e++) {
                float2 vf = __half22float2(hp[e]);
                o[j * 8 + 2 * e]     += p * vf.x;
                o[j * 8 + 2 * e + 1] += p * vf.y;
            }
        }
    }

    if (n == Nseq - 1) {
#pragma unroll
        for (int w = 0; w <= W2; w++)
            attn_last[(b * Hn + h) * (W2 + 1) + w] = s[w] * inv;
    }

    // ---- write O: regs -> smem (reuse sK) -> coalesced gmem ----
    __syncthreads();   // all reads of sK done
#pragma unroll
    for (int j = 0; j < 8; j++) {
        uint4 raw;
        __half2* hp = (__half2*)&raw;
#pragma unroll
        for (int e = 0; e < 4; e++)
            hp[e] = __floats2half2_rn(o[j * 8 + 2 * e], o[j * 8 + 2 * e + 1]);
        ((uint4*)(sK + t * AT_PITCH))[j] = raw;
    }
    __syncthreads();
    for (int i = t; i < 256 * 8; i += 256) {
        int r = i >> 3, c = i & 7;
        *(uint4*)(g_Oh + rowbase + (size_t)(n0 + r) * Cdim + c * 8) =
            *(const uint4*)(sK + r * AT_PITCH + c * 8);
    }
}

// ---------------------------------------------------------------------------
// Launch: fp16 prepass -> QKV (z=3) -> attention -> output projection.
// d_out layout: [out: 8192*1024 floats][attn_last: 2*16*11 floats]
// ---------------------------------------------------------------------------
extern "C" void kernel_launch(void* const* d_in, const int* in_sizes, int n_in,
                              void* d_out, int out_size)
{
    const float* q  = (const float*)d_in[0];
    const float* Wq = (const float*)d_in[1];
    const float* bq = (const float*)d_in[2];
    const float* Wk = (const float*)d_in[3];
    const float* bk = (const float*)d_in[4];
    const float* Wv = (const float*)d_in[5];
    const float* bv = (const float*)d_in[6];
    const float* Wo = (const float*)d_in[7];
    const float* bo = (const float*)d_in[8];
    float* out = (float*)d_out;

    cudaFuncSetAttribute(qkv_gemm,
                         cudaFuncAttributeMaxDynamicSharedMemorySize,
                         SMEM_BYTES);
    cudaFuncSetAttribute(out_gemm_kernel,
                         cudaFuncAttributeMaxDynamicSharedMemorySize,
                         SMEM_BYTES);
    cudaFuncSetAttribute(attn_kernel,
                         cudaFuncAttributeMaxDynamicSharedMemorySize,
                         AT_SMEM);

    // prepass: round X + 4 weights to fp16 once
    to_half_kernel<<<dim3(256, 5), 256>>>(q, Wq, Wk, Wv, Wo);

    dim3 blk(256);
    dim3 g_qkv(Cdim / 256, MROWS / 128, 3);   // (4, 64, 3)
    qkv_gemm<<<g_qkv, blk, SMEM_BYTES>>>(bq, bk, bv);

    attn_kernel<<<dim3(Nseq / 256, Hn, Bdim), 256, AT_SMEM>>>(out + OUT_ELEMS);

    dim3 g_o(Cdim / 256, MROWS / 128, 1);
    out_gemm_kernel<<<g_o, blk, SMEM_BYTES>>>(bo, out);
}

// round 17
// speedup vs baseline: 4.6613x; 1.0430x over previous
#include <cuda_runtime.h>
#include <cuda_fp16.h>
#include <cstdint>
#include <math.h>

// Problem constants
#define Bdim 2
#define Nseq 4096
#define Cdim 1024
#define Hn   16
#define Dd   64
#define W2   10
#define WW   21

#define MROWS (Bdim * Nseq)          // 8192
#define OUT_ELEMS (MROWS * Cdim)     // 8,388,608
#define W_ELEMS  (Cdim * Cdim)       // 1,048,576

// Scratch: device globals (no allocations allowed in kernel_launch)
__device__ __half g_X[OUT_ELEMS];
__device__ __half g_W[4][W_ELEMS];   // Wq, Wk, Wv, Wo
__device__ __half g_Qh[OUT_ELEMS];
__device__ __half g_Kh[OUT_ELEMS];
__device__ __half g_Vh[OUT_ELEMS];
__device__ __half g_Oh[OUT_ELEMS];   // attn out (fp16), feeds out-projection

// ---------------------------------------------------------------------------
// Prepass: round fp32 -> fp16 (RN) once.
// ---------------------------------------------------------------------------
__global__ __launch_bounds__(256) void to_half_kernel(
    const float* __restrict__ X,
    const float* __restrict__ Wq, const float* __restrict__ Wk,
    const float* __restrict__ Wv, const float* __restrict__ Wo)
{
    const float* src; __half* dst; int n4;
    switch (blockIdx.y) {
        case 0: src = X;  dst = g_X;    n4 = OUT_ELEMS / 4; break;
        case 1: src = Wq; dst = g_W[0]; n4 = W_ELEMS / 4;   break;
        case 2: src = Wk; dst = g_W[1]; n4 = W_ELEMS / 4;   break;
        case 3: src = Wv; dst = g_W[2]; n4 = W_ELEMS / 4;   break;
        default: src = Wo; dst = g_W[3]; n4 = W_ELEMS / 4;  break;
    }
    const int stride = gridDim.x * blockDim.x;
    for (int i = blockIdx.x * blockDim.x + threadIdx.x; i < n4; i += stride) {
        float4 v = ((const float4*)src)[i];
        ((__half2*)dst)[2 * i]     = __floats2half2_rn(v.x, v.y);
        ((__half2*)dst)[2 * i + 1] = __floats2half2_rn(v.z, v.w);
    }
}

// ---------------------------------------------------------------------------
// fp16 GEMM via hand-rolled ldmatrix + mma.sync.m16n8k16 (fp32 accumulate),
// 2-stage cp.async, K-tile 128, register double-buffered fragments:
//   C[m, n] = sum_k A[m, k] * W[n, k] + bias[n]
// Block 128(M) x 256(N); 256 thr = 8 warps as 2(M) x 4(N); warp tile 64x64.
// W is [n][k] (k contiguous) == col-major B for mma -> B fragments come from
// PLAIN (non-trans) ldmatrix with smem rows = n, cols = k.
// ---------------------------------------------------------------------------
#define KT       128                     // halfs per K-tile
#define NTt      (Cdim / KT)             // 8
#define PITCH    136                     // 128+8 pad halfs; 17x16B rows ->
                                         // ldmatrix phases conflict-free
#define TILE_A_H (128 * PITCH)
#define TILE_B_H (256 * PITCH)
#define STAGE_H  (TILE_A_H + TILE_B_H)   // 52224 halfs
#define SMEM_BYTES (2 * STAGE_H * 2)     // 208896 B

__device__ __forceinline__ void cp16(void* smem_dst, const void* gmem_src)
{
    unsigned d = (unsigned)__cvta_generic_to_shared(smem_dst);
    asm volatile("cp.async.cg.shared.global [%0], [%1], 16;\n"
                 :: "r"(d), "l"(gmem_src));
}

__device__ __forceinline__ void ldsm_x4(uint32_t* r, unsigned addr)
{
    asm volatile(
        "ldmatrix.sync.aligned.m8n8.x4.shared.b16 {%0,%1,%2,%3}, [%4];"
        : "=r"(r[0]), "=r"(r[1]), "=r"(r[2]), "=r"(r[3]) : "r"(addr));
}

__device__ __forceinline__ void mma16816(float* d, const uint32_t* a,
                                         const uint32_t* b)
{
    asm volatile(
        "mma.sync.aligned.m16n8k16.row.col.f32.f16.f16.f32 "
        "{%0,%1,%2,%3}, {%4,%5,%6,%7}, {%8,%9}, {%0,%1,%2,%3};"
        : "+f"(d[0]), "+f"(d[1]), "+f"(d[2]), "+f"(d[3])
        : "r"(a[0]), "r"(a[1]), "r"(a[2]), "r"(a[3]), "r"(b[0]), "r"(b[1]));
}

template <typename OutT>
__device__ __forceinline__ void gemm_block_f16(
    const __half* __restrict__ A, const __half* __restrict__ W,
    const float* __restrict__ bias, OutT* __restrict__ C)
{
    constexpr int K  = Cdim;
    constexpr int Nf = Cdim;

    extern __shared__ __half smem[];
    const unsigned sbase = (unsigned)__cvta_generic_to_shared(smem);

    const int tid  = threadIdx.x;        // 256 threads
    const int wid  = tid >> 5;
    const int lane = tid & 31;
    const int wr   = wid >> 2;           // 0..1 -> 64 rows each
    const int wc   = wid & 3;            // 0..3 -> 64 cols each
    const int rowBase = blockIdx.y * 128;
    const int colBase = blockIdx.x * 256;
    const int qr = lane >> 2, qc = lane & 3;

    // ---- accumulators, bias-initialized in registers ----
    float acc[4][8][4];
#pragma unroll
    for (int jn = 0; jn < 8; jn++) {
        float2 bv = *(const float2*)(bias + colBase + wc * 64 + jn * 8 + qc * 2);
#pragma unroll
        for (int i = 0; i < 4; i++) {
            acc[i][jn][0] = bv.x; acc[i][jn][1] = bv.y;
            acc[i][jn][2] = bv.x; acc[i][jn][3] = bv.y;
        }
    }

    // ---- per-thread ldmatrix base offsets (half units, no stage/kk) ----
    // A (rows = m): m0: lanes 0-15 rows 0-15 @k0; lanes 16-31 same rows @k8
    //   -> regs {a0,a1,a2,a3} = (r,k0-7),(r+8,k0-7),(r,k8-15),(r+8,k8-15)
    // B (rows = n): lanes 0-7 n0-7@k0; 8-15 n0-7@k8; 16-23 n8-15@k0;
    //   24-31 n8-15@k8 -> regs {b0,b1} n-tile0, {b2,b3} n-tile1 (non-trans)
    unsigned aOff[4], bOff[4];
#pragma unroll
    for (int i = 0; i < 4; i++)
        aOff[i] = (unsigned)((wr * 64 + i * 16 + (lane & 15)) * PITCH
                             + 8 * (lane >> 4));
#pragma unroll
    for (int j = 0; j < 4; j++)
        bOff[j] = (unsigned)(TILE_A_H
                             + (wc * 64 + j * 16 + (lane & 7)
                                + 8 * ((lane >> 4) & 1)) * PITCH
                             + 8 * ((lane >> 3) & 1));

    // ---- async copy: A 128x128 = 2048 16B chunks (8/t); B 256x128 (16/t) ---
    // prefetch tile 0 into stage 0
    {
        __half* As = smem;
        __half* Bs = smem + TILE_A_H;
#pragma unroll
        for (int j = 0; j < 8; j++) {
            int c = tid + j * 256, r = c >> 4, col = (c & 15) << 3;
            cp16(&As[r * PITCH + col], A + (size_t)(rowBase + r) * K + col);
        }
#pragma unroll
        for (int j = 0; j < 16; j++) {
            int c = tid + j * 256, r = c >> 4, col = (c & 15) << 3;
            cp16(&Bs[r * PITCH + col], W + (size_t)(colBase + r) * K + col);
        }
        asm volatile("cp.async.commit_group;\n" ::: "memory");
    }

    uint32_t afr[2][4][4], bfr[2][4][4];

    for (int kt = 0; kt < NTt; kt++) {
        if (kt + 1 < NTt) {
            __half* As = smem + ((kt + 1) & 1) * STAGE_H;
            __half* Bs = As + TILE_A_H;
            const int k0 = (kt + 1) * KT;
#pragma unroll
            for (int j = 0; j < 8; j++) {
                int c = tid + j * 256, r = c >> 4, col = (c & 15) << 3;
                cp16(&As[r * PITCH + col],
                     A + (size_t)(rowBase + r) * K + k0 + col);
            }
#pragma unroll
            for (int j = 0; j < 16; j++) {
                int c = tid + j * 256, r = c >> 4, col = (c & 15) << 3;
                cp16(&Bs[r * PITCH + col],
                     W + (size_t)(colBase + r) * K + k0 + col);
            }
            asm volatile("cp.async.commit_group;\n" ::: "memory");
            asm volatile("cp.async.wait_group 1;\n" ::: "memory");
        } else {
            asm volatile("cp.async.wait_group 0;\n" ::: "memory");
        }
        __syncthreads();   // current stage visible

        const unsigned stB = sbase + ((kt & 1) ? STAGE_H * 2u : 0u);

        // fragments for kk = 0
#pragma unroll
        for (int i = 0; i < 4; i++) ldsm_x4(afr[0][i], stB + 2u * aOff[i]);
#pragma unroll
        for (int j = 0; j < 4; j++) ldsm_x4(bfr[0][j], stB + 2u * bOff[j]);

        int buf = 0;
#pragma unroll
        for (int kk16 = 0; kk16 < KT / 16; kk16++) {
            if (kk16 + 1 < KT / 16) {
                const unsigned ko = 2u * (unsigned)((kk16 + 1) * 16);
#pragma unroll
                for (int i = 0; i < 4; i++)
                    ldsm_x4(afr[buf ^ 1][i], stB + 2u * aOff[i] + ko);
#pragma unroll
                for (int j = 0; j < 4; j++)
                    ldsm_x4(bfr[buf ^ 1][j], stB + 2u * bOff[j] + ko);
            }
#pragma unroll
            for (int i = 0; i < 4; i++)
#pragma unroll
                for (int j = 0; j < 4; j++) {
                    mma16816(acc[i][2 * j],     afr[buf][i], &bfr[buf][j][0]);
                    mma16816(acc[i][2 * j + 1], afr[buf][i], &bfr[buf][j][2]);
                }
            buf ^= 1;
        }
        __syncthreads();   // all warps done with this stage before refill
    }

    // ---- epilogue: m16n8 acc mapping -> direct gmem stores ----
    // thread (qr, qc): regs {0,1} -> row qr,    cols 2qc, 2qc+1
    //                  regs {2,3} -> row qr+8,  same cols
#pragma unroll
    for (int i = 0; i < 4; i++)
#pragma unroll
        for (int jn = 0; jn < 8; jn++) {
            int r = rowBase + wr * 64 + i * 16 + qr;
            int c = colBase + wc * 64 + jn * 8 + qc * 2;
            if constexpr (sizeof(OutT) == 4) {
                *(float2*)((float*)C + (size_t)r * Nf + c) =
                    make_float2(acc[i][jn][0], acc[i][jn][1]);
                *(float2*)((float*)C + (size_t)(r + 8) * Nf + c) =
                    make_float2(acc[i][jn][2], acc[i][jn][3]);
            } else {
                *(__half2*)((__half*)C + (size_t)r * Nf + c) =
                    __floats2half2_rn(acc[i][jn][0], acc[i][jn][1]);
                *(__half2*)((__half*)C + (size_t)(r + 8) * Nf + c) =
                    __floats2half2_rn(acc[i][jn][2], acc[i][jn][3]);
            }
        }
}

// QKV: one launch, blockIdx.z selects {Q, K, V}; outputs fp16
__global__ __launch_bounds__(256) void qkv_gemm(
    const float* __restrict__ bq, const float* __restrict__ bk,
    const float* __restrict__ bv)
{
    const float* b; __half* out;
    if (blockIdx.z == 0)      { b = bq; out = g_Qh; }
    else if (blockIdx.z == 1) { b = bk; out = g_Kh; }
    else                      { b = bv; out = g_Vh; }
    gemm_block_f16<__half>(g_X, g_W[blockIdx.z], b, out);
}

__global__ __launch_bounds__(256) void out_gemm_kernel(
    const float* __restrict__ bo, float* __restrict__ out)
{
    gemm_block_f16<float>(g_Oh, g_W[3], bo, out);
}

// ---------------------------------------------------------------------------
// Local window attention, thread-per-query with smem-staged K/V (unchanged).
// ---------------------------------------------------------------------------
#define AT_ROWS  276                     // 256 + 2*W2
#define AT_PITCH 72                      // halfs; 144B rows, 16B aligned
#define AT_SMEM  (2 * AT_ROWS * AT_PITCH * 2)   // 79488 B

__global__ __launch_bounds__(256) void attn_kernel(float* __restrict__ attn_last)
{
    extern __shared__ __half asm_[];
    __half* sK = asm_;
    __half* sV = asm_ + AT_ROWS * AT_PITCH;

    const int t  = threadIdx.x;
    const int n0 = blockIdx.x << 8;        // 256 queries per block
    const int h  = blockIdx.y;
    const int b  = blockIdx.z;
    const int n  = n0 + t;
    const size_t rowbase = (size_t)b * Nseq * Cdim + h * Dd;

    // ---- stage Q coalesced into sV (uint4 = 8 halfs), then to registers ----
    for (int i = t; i < 256 * 8; i += 256) {
        int r = i >> 3, c = i & 7;
        *(uint4*)(sV + r * AT_PITCH + c * 8) =
            *(const uint4*)(g_Qh + rowbase + (size_t)(n0 + r) * Cdim + c * 8);
    }
    __syncthreads();
    float q[64];
#pragma unroll
    for (int j = 0; j < 8; j++) {
        uint4 raw = ((const uint4*)(sV + t * AT_PITCH))[j];
        const __half2* hp = (const __half2*)&raw;
#pragma unroll
        for (int e = 0; e < 4; e++) {
            float2 f = __half22float2(hp[e]);
            q[j * 8 + 2 * e]     = f.x;
            q[j * 8 + 2 * e + 1] = f.y;
        }
    }
    __syncthreads();

    // ---- stage K and V window (zero-filled outside [0, N)), uint4 grain ----
    for (int i = t; i < AT_ROWS * 8; i += 256) {
        int r = i >> 3, c = i & 7;
        int gr = n0 - W2 + r;
        uint4 kw = make_uint4(0, 0, 0, 0), vw = make_uint4(0, 0, 0, 0);
        if ((unsigned)gr < (unsigned)Nseq) {
            size_t off = rowbase + (size_t)gr * Cdim + c * 8;
            kw = *(const uint4*)(g_Kh + off);
            vw = *(const uint4*)(g_Vh + off);
        }
        *(uint4*)(sK + r * AT_PITCH + c * 8) = kw;
        *(uint4*)(sV + r * AT_PITCH + c * 8) = vw;
    }
    __syncthreads();

    // ---- scores ----
    float s[WW];
#pragma unroll
    for (int w = 0; w < WW; w++) {
        const int pos = n - W2 + w;
        const uint4* kr = (const uint4*)(sK + (t + w) * AT_PITCH);
        float d = 0.f;
#pragma unroll
        for (int j = 0; j < 8; j++) {
            uint4 raw = kr[j];
            const __half2* hp = (const __half2*)&raw;
#pragma unroll
            for (int e = 0; e < 4; e++) {
                float2 kf = __half22float2(hp[e]);
                d += q[j * 8 + 2 * e] * kf.x + q[j * 8 + 2 * e + 1] * kf.y;
            }
        }
        s[w] = ((unsigned)pos < (unsigned)Nseq) ? d * 0.125f : -INFINITY;
    }

    float m = s[0];
#pragma unroll
    for (int w = 1; w < WW; w++) m = fmaxf(m, s[w]);
    float sum = 0.f;
#pragma unroll
    for (int w = 0; w < WW; w++) {
        const float e = __expf(s[w] - m);
        s[w] = e;
        sum += e;
    }
    const float inv = 1.f / sum;

    // ---- weighted V sum ----
    float o[64];
#pragma unroll
    for (int j = 0; j < 64; j++) o[j] = 0.f;
#pragma unroll
    for (int w = 0; w < WW; w++) {
        const float p = s[w] * inv;
        const uint4* vr = (const uint4*)(sV + (t + w) * AT_PITCH);
#pragma unroll
        for (int j = 0; j < 8; j++) {
            uint4 raw = vr[j];
            const __half2* hp = (const __half2*)&raw;
#pragma unroll
            for (int e = 0; e < 4; e++) {
                float2 vf = __half22float2(hp[e]);
                o[j * 8 + 2 * e]     += p * vf.x;
                o[j * 8 + 2 * e + 1] += p * vf.y;
            }
        }
    }

    if (n == Nseq - 1) {
#pragma unroll
        for (int w = 0; w <= W2; w++)
            attn_last[(b * Hn + h) * (W2 + 1) + w] = s[w] * inv;
    }

    // ---- write O: regs -> smem (reuse sK) -> coalesced gmem ----
    __syncthreads();
#pragma unroll
    for (int j = 0; j < 8; j++) {
        uint4 raw;
        __half2* hp = (__half2*)&raw;
#pragma unroll
        for (int e = 0; e < 4; e++)
            hp[e] = __floats2half2_rn(o[j * 8 + 2 * e], o[j * 8 + 2 * e + 1]);
        ((uint4*)(sK + t * AT_PITCH))[j] = raw;
    }
    __syncthreads();
    for (int i = t; i < 256 * 8; i += 256) {
        int r = i >> 3, c = i & 7;
        *(uint4*)(g_Oh + rowbase + (size_t)(n0 + r) * Cdim + c * 8) =
            *(const uint4*)(sK + r * AT_PITCH + c * 8);
    }
}

// ---------------------------------------------------------------------------
// Launch: fp16 prepass -> QKV (z=3) -> attention -> output projection.
// d_out layout: [out: 8192*1024 floats][attn_last: 2*16*11 floats]
// ---------------------------------------------------------------------------
extern "C" void kernel_launch(void* const* d_in, const int* in_sizes, int n_in,
                              void* d_out, int out_size)
{
    const float* q  = (const float*)d_in[0];
    const float* Wq = (const float*)d_in[1];
    const float* bq = (const float*)d_in[2];
    const float* Wk = (const float*)d_in[3];
    const float* bk = (const float*)d_in[4];
    const float* Wv = (const float*)d_in[5];
    const float* bv = (const float*)d_in[6];
    const float* Wo = (const float*)d_in[7];
    const float* bo = (const float*)d_in[8];
    float* out = (float*)d_out;

    cudaFuncSetAttribute(qkv_gemm,
                         cudaFuncAttributeMaxDynamicSharedMemorySize,
                         SMEM_BYTES);
    cudaFuncSetAttribute(out_gemm_kernel,
                         cudaFuncAttributeMaxDynamicSharedMemorySize,
                         SMEM_BYTES);
    cudaFuncSetAttribute(attn_kernel,
                         cudaFuncAttributeMaxDynamicSharedMemorySize,
                         AT_SMEM);

    // prepass: round X + 4 weights to fp16 once
    to_half_kernel<<<dim3(256, 5), 256>>>(q, Wq, Wk, Wv, Wo);

    dim3 blk(256);
    dim3 g_qkv(Cdim / 256, MROWS / 128, 3);   // (4, 64, 3)
    qkv_gemm<<<g_qkv, blk, SMEM_BYTES>>>(bq, bk, bv);

    attn_kernel<<<dim3(Nseq / 256, Hn, Bdim), 256, AT_SMEM>>>(out + OUT_ELEMS);

    dim3 g_o(Cdim / 256, MROWS / 128, 1);
    out_gemm_kernel<<<g_o, blk, SMEM_BYTES>>>(bo, out);
}